// round 1
// baseline (speedup 1.0000x reference)
#include <cuda_runtime.h>
#include <math.h>
#include <float.h>

// Problem constants
#define T_LEN 2048
#define DIMM  256
#define HQ_N  32
#define HK_N  8
#define DH_N  128
#define QDIM  (HQ_N * DH_N)   // 4096
#define KDIM  (HK_N * DH_N)   // 1024

// Scratch (no cudaMalloc allowed)
__device__ __align__(16) float g_Q[T_LEN * QDIM];
__device__ __align__(16) float g_K[T_LEN * KDIM];
__device__ __align__(16) float g_V[T_LEN * KDIM];
__device__ __align__(16) float g_O[T_LEN * QDIM];
__device__ double g_invf[DH_N];

// ---------------------------------------------------------------------------
// inv_freq precompute in double (accuracy: positions up to 8191 rad)
// ---------------------------------------------------------------------------
__global__ void invf_kernel() {
    int d = threadIdx.x;
    if (d < DH_N) g_invf[d] = pow(10000.0, -(double)d / 128.0);
}

// ---------------------------------------------------------------------------
// RoPE in place on [T][nh*128]; pos = 6144 + t (cache 8192, last T positions)
// out[d]      = x[d]*cos(f_d)     - x[d+64]*sin(f_d)       (d < 64)
// out[d+64]   = x[d+64]*cos(f_d64)+ x[d]*sin(f_d64)
// ---------------------------------------------------------------------------
__global__ void rope_kernel(float* __restrict__ X, int nh) {
    int idx = blockIdx.x * blockDim.x + threadIdx.x;
    int total = T_LEN * nh * 64;
    if (idx >= total) return;
    int d = idx & 63;
    int h = (idx >> 6) % nh;
    int t = idx / (64 * nh);

    float* row = X + (size_t)t * nh * DH_N + (size_t)h * DH_N;
    double pos = (double)(6144 + t);
    double f1 = pos * g_invf[d];
    double f2 = pos * g_invf[d + 64];
    const double inv2pi = 0.15915494309189535;
    const double twopi  = 6.283185307179586;
    f1 -= floor(f1 * inv2pi) * twopi;
    f2 -= floor(f2 * inv2pi) * twopi;
    float s1, c1, s2, c2;
    sincosf((float)f1, &s1, &c1);
    sincosf((float)f2, &s2, &c2);
    float x1 = row[d], x2 = row[d + 64];
    row[d]      = x1 * c1 - x2 * s1;
    row[d + 64] = x2 * c2 + x1 * s2;
}

// ---------------------------------------------------------------------------
// Generic fp32 GEMM: C[M,N] = A[M,K] @ B[K,N], all row-major.
// 64x64 tile, BK=16, 256 threads, 4x4 microtile. M,N %64==0, K %16==0.
// ---------------------------------------------------------------------------
__global__ void gemm64(const float* __restrict__ A, const float* __restrict__ B,
                       float* __restrict__ C, int M, int N, int K) {
    __shared__ float As[64][17];
    __shared__ float Bs[16][64];

    int tid = threadIdx.x;
    int tx = tid & 15, ty = tid >> 4;
    int m0 = blockIdx.y * 64, n0 = blockIdx.x * 64;

    int ar = tid >> 2,  ac = (tid & 3) << 2;   // A tile load: 64x16
    int br = tid >> 4,  bc = (tid & 15) << 2;  // B tile load: 16x64

    float acc[4][4];
#pragma unroll
    for (int i = 0; i < 4; i++)
#pragma unroll
        for (int j = 0; j < 4; j++) acc[i][j] = 0.f;

    int ty4 = ty << 2, tx4 = tx << 2;

    for (int k0 = 0; k0 < K; k0 += 16) {
        float4 a4 = *(const float4*)&A[(size_t)(m0 + ar) * K + k0 + ac];
        As[ar][ac + 0] = a4.x; As[ar][ac + 1] = a4.y;
        As[ar][ac + 2] = a4.z; As[ar][ac + 3] = a4.w;
        float4 b4 = *(const float4*)&B[(size_t)(k0 + br) * N + n0 + bc];
        *(float4*)&Bs[br][bc] = b4;
        __syncthreads();

#pragma unroll
        for (int kk = 0; kk < 16; kk++) {
            float a0 = As[ty4 + 0][kk];
            float a1 = As[ty4 + 1][kk];
            float a2 = As[ty4 + 2][kk];
            float a3 = As[ty4 + 3][kk];
            float4 b = *(const float4*)&Bs[kk][tx4];
            acc[0][0] += a0 * b.x; acc[0][1] += a0 * b.y; acc[0][2] += a0 * b.z; acc[0][3] += a0 * b.w;
            acc[1][0] += a1 * b.x; acc[1][1] += a1 * b.y; acc[1][2] += a1 * b.z; acc[1][3] += a1 * b.w;
            acc[2][0] += a2 * b.x; acc[2][1] += a2 * b.y; acc[2][2] += a2 * b.z; acc[2][3] += a2 * b.w;
            acc[3][0] += a3 * b.x; acc[3][1] += a3 * b.y; acc[3][2] += a3 * b.z; acc[3][3] += a3 * b.w;
        }
        __syncthreads();
    }

#pragma unroll
    for (int i = 0; i < 4; i++) {
        float4 r = make_float4(acc[i][0], acc[i][1], acc[i][2], acc[i][3]);
        *(float4*)&C[(size_t)(m0 + ty4 + i) * N + n0 + tx4] = r;
    }
}

// ---------------------------------------------------------------------------
// Flash attention, fp32, causal. One block per (64-query tile, q-head).
// Q:[T][4096] (head hq at col hq*128), K/V:[T][1024] (kv head g = hq/4).
// Threads: 256 as 16x16; thread (ty,tx): S microtile rows ty*4..+3, cols tx*4..+3;
// O microtile rows ty*4..+3, cols tx*8..+7. P exchanged via warp shuffles.
// ---------------------------------------------------------------------------
#define ATTN_SMEM_FLOATS (2 * 64 * 129 + 64 * 128)
#define ATTN_SMEM_BYTES  (ATTN_SMEM_FLOATS * 4)

__global__ void attn_kernel(const float* __restrict__ Q, const float* __restrict__ K,
                            const float* __restrict__ V, float* __restrict__ O) {
    extern __shared__ float sm[];
    float (*sQ)[129] = (float (*)[129])sm;
    float (*sK)[129] = (float (*)[129])(sm + 64 * 129);
    float (*sV)[128] = (float (*)[128])(sm + 2 * 64 * 129);

    const int tid = threadIdx.x;
    const int tx = tid & 15, ty = tid >> 4;
    const int tx4 = tx << 2, ty4 = ty << 2, tx8 = tx << 3;
    const int lane = tid & 31;
    const int qt = blockIdx.x;       // query tile (64 rows)
    const int hq = blockIdx.y;       // query head
    const int g  = hq >> 2;          // kv head
    const float scale = 0.08838834764831845f;   // 1/sqrt(128)

    // Load Q tile [64][128]
    for (int idx = tid; idx < 64 * 32; idx += 256) {
        int r = idx >> 5, c = (idx & 31) << 2;
        float4 t4 = *(const float4*)&Q[(size_t)(qt * 64 + r) * QDIM + hq * DH_N + c];
        sQ[r][c + 0] = t4.x; sQ[r][c + 1] = t4.y; sQ[r][c + 2] = t4.z; sQ[r][c + 3] = t4.w;
    }

    float m[4], l[4], o[4][8];
#pragma unroll
    for (int i = 0; i < 4; i++) {
        m[i] = -FLT_MAX; l[i] = 0.f;
#pragma unroll
        for (int j = 0; j < 8; j++) o[i][j] = 0.f;
    }

    for (int kb = 0; kb <= qt; kb++) {
        // Load K,V tiles [64][128]
        for (int idx = tid; idx < 64 * 32; idx += 256) {
            int r = idx >> 5, c = (idx & 31) << 2;
            size_t off = (size_t)(kb * 64 + r) * KDIM + g * DH_N + c;
            float4 k4 = *(const float4*)&K[off];
            sK[r][c + 0] = k4.x; sK[r][c + 1] = k4.y; sK[r][c + 2] = k4.z; sK[r][c + 3] = k4.w;
            float4 v4 = *(const float4*)&V[off];
            *(float4*)&sV[r][c] = v4;
        }
        __syncthreads();

        // S = Q K^T  (4x4 microtile per thread)
        float s[4][4];
#pragma unroll
        for (int i = 0; i < 4; i++)
#pragma unroll
            for (int j = 0; j < 4; j++) s[i][j] = 0.f;

        for (int d = 0; d < 128; d++) {
            float qv[4], kv[4];
#pragma unroll
            for (int i = 0; i < 4; i++) qv[i] = sQ[ty4 + i][d];
#pragma unroll
            for (int j = 0; j < 4; j++) kv[j] = sK[tx4 + j][d];
#pragma unroll
            for (int i = 0; i < 4; i++)
#pragma unroll
                for (int j = 0; j < 4; j++) s[i][j] = fmaf(qv[i], kv[j], s[i][j]);
        }

        // Causal mask on the diagonal block
        if (kb == qt) {
#pragma unroll
            for (int i = 0; i < 4; i++)
#pragma unroll
                for (int j = 0; j < 4; j++)
                    if (tx4 + j > ty4 + i) s[i][j] = -FLT_MAX;
        }

        // Online softmax: row max over 16 lanes, rescale, exp, row sum
        float mnew[4], alpha[4];
#pragma unroll
        for (int i = 0; i < 4; i++) {
            float mm = fmaxf(fmaxf(s[i][0], s[i][1]), fmaxf(s[i][2], s[i][3]));
#pragma unroll
            for (int off = 1; off < 16; off <<= 1)
                mm = fmaxf(mm, __shfl_xor_sync(0xffffffffu, mm, off));
            mnew[i] = fmaxf(m[i], mm);
            alpha[i] = expf((m[i] - mnew[i]) * scale);
            m[i] = mnew[i];
        }
        float lloc[4];
#pragma unroll
        for (int i = 0; i < 4; i++) {
            lloc[i] = 0.f;
#pragma unroll
            for (int j = 0; j < 4; j++) {
                float p = expf((s[i][j] - mnew[i]) * scale);
                s[i][j] = p;                 // s now holds P
                lloc[i] += p;
            }
#pragma unroll
            for (int off = 1; off < 16; off <<= 1)
                lloc[i] += __shfl_xor_sync(0xffffffffu, lloc[i], off);
            l[i] = l[i] * alpha[i] + lloc[i];
#pragma unroll
            for (int j = 0; j < 8; j++) o[i][j] *= alpha[i];
        }

        // O += P @ V ; P broadcast via warp shuffle (owner lane = (lane&16)|(kk>>2))
#pragma unroll
        for (int kk = 0; kk < 64; kk++) {
            int src = (lane & 16) | (kk >> 2);
            float pv0 = __shfl_sync(0xffffffffu, s[0][kk & 3], src);
            float pv1 = __shfl_sync(0xffffffffu, s[1][kk & 3], src);
            float pv2 = __shfl_sync(0xffffffffu, s[2][kk & 3], src);
            float pv3 = __shfl_sync(0xffffffffu, s[3][kk & 3], src);
            float4 va = *(const float4*)&sV[kk][tx8];
            float4 vb = *(const float4*)&sV[kk][tx8 + 4];
            o[0][0] += pv0 * va.x; o[0][1] += pv0 * va.y; o[0][2] += pv0 * va.z; o[0][3] += pv0 * va.w;
            o[0][4] += pv0 * vb.x; o[0][5] += pv0 * vb.y; o[0][6] += pv0 * vb.z; o[0][7] += pv0 * vb.w;
            o[1][0] += pv1 * va.x; o[1][1] += pv1 * va.y; o[1][2] += pv1 * va.z; o[1][3] += pv1 * va.w;
            o[1][4] += pv1 * vb.x; o[1][5] += pv1 * vb.y; o[1][6] += pv1 * vb.z; o[1][7] += pv1 * vb.w;
            o[2][0] += pv2 * va.x; o[2][1] += pv2 * va.y; o[2][2] += pv2 * va.z; o[2][3] += pv2 * va.w;
            o[2][4] += pv2 * vb.x; o[2][5] += pv2 * vb.y; o[2][6] += pv2 * vb.z; o[2][7] += pv2 * vb.w;
            o[3][0] += pv3 * va.x; o[3][1] += pv3 * va.y; o[3][2] += pv3 * va.z; o[3][3] += pv3 * va.w;
            o[3][4] += pv3 * vb.x; o[3][5] += pv3 * vb.y; o[3][6] += pv3 * vb.z; o[3][7] += pv3 * vb.w;
        }
        __syncthreads();   // protect sK/sV before next tile load
    }

    // Normalize and write O[t][hq*128 + d]
#pragma unroll
    for (int i = 0; i < 4; i++) {
        float inv = 1.0f / l[i];
        int row = qt * 64 + ty4 + i;
        float4 r0 = make_float4(o[i][0] * inv, o[i][1] * inv, o[i][2] * inv, o[i][3] * inv);
        float4 r1 = make_float4(o[i][4] * inv, o[i][5] * inv, o[i][6] * inv, o[i][7] * inv);
        size_t base = (size_t)row * QDIM + hq * DH_N + tx8;
        *(float4*)&O[base]     = r0;
        *(float4*)&O[base + 4] = r1;
    }
}

// ---------------------------------------------------------------------------
// Launch
// ---------------------------------------------------------------------------
extern "C" void kernel_launch(void* const* d_in, const int* in_sizes, int n_in,
                              void* d_out, int out_size) {
    const float* q  = (const float*)d_in[0];
    const float* k  = (const float*)d_in[1];
    const float* v  = (const float*)d_in[2];
    // d_in[3] = mask (causal, reconstructed analytically)
    const float* Wq = (const float*)d_in[4];
    const float* Wk = (const float*)d_in[5];
    const float* Wv = (const float*)d_in[6];
    const float* Wo = (const float*)d_in[7];
    float* out = (float*)d_out;

    float *Qb, *Kb, *Vb, *Ob;
    cudaGetSymbolAddress((void**)&Qb, g_Q);
    cudaGetSymbolAddress((void**)&Kb, g_K);
    cudaGetSymbolAddress((void**)&Vb, g_V);
    cudaGetSymbolAddress((void**)&Ob, g_O);

    cudaFuncSetAttribute(attn_kernel, cudaFuncAttributeMaxDynamicSharedMemorySize,
                         ATTN_SMEM_BYTES);

    invf_kernel<<<1, 128>>>();

    gemm64<<<dim3(QDIM / 64, T_LEN / 64), 256>>>(q, Wq, Qb, T_LEN, QDIM, DIMM);
    gemm64<<<dim3(KDIM / 64, T_LEN / 64), 256>>>(k, Wk, Kb, T_LEN, KDIM, DIMM);
    gemm64<<<dim3(KDIM / 64, T_LEN / 64), 256>>>(v, Wv, Vb, T_LEN, KDIM, DIMM);

    rope_kernel<<<(T_LEN * HQ_N * 64 + 255) / 256, 256>>>(Qb, HQ_N);
    rope_kernel<<<(T_LEN * HK_N * 64 + 255) / 256, 256>>>(Kb, HK_N);
    rope_kernel<<<(T_LEN * HK_N * 64 + 255) / 256, 256>>>(Vb, HK_N);

    attn_kernel<<<dim3(T_LEN / 64, HQ_N), 256, ATTN_SMEM_BYTES>>>(Qb, Kb, Vb, Ob);

    gemm64<<<dim3(DIMM / 64, T_LEN / 64), 256>>>(Ob, Wo, out, T_LEN, DIMM, QDIM);
}

// round 3
// speedup vs baseline: 2.8022x; 2.8022x over previous
#include <cuda_runtime.h>
#include <cuda_fp16.h>
#include <math.h>
#include <float.h>
#include <stdint.h>

// ---------------------------------------------------------------------------
// Problem constants
// ---------------------------------------------------------------------------
#define T_LEN 2048
#define DIMM  256
#define HQ_N  32
#define HK_N  8
#define DH_N  128
#define QDIM  (HQ_N * DH_N)   // 4096
#define KDIM  (HK_N * DH_N)   // 1024

// Scratch (no cudaMalloc allowed)
__device__ __align__(16) float  g_Q[T_LEN * QDIM];
__device__ __align__(16) float  g_K[T_LEN * KDIM];
__device__ __align__(16) float  g_V[T_LEN * KDIM];
__device__ __align__(16) __half g_Qh[T_LEN * QDIM];
__device__ __align__(16) __half g_Kh[T_LEN * KDIM];
__device__ __align__(16) __half g_Vh[T_LEN * KDIM];
__device__ __align__(16) float  g_O[T_LEN * QDIM];
__device__ double g_invf[DH_N];

// ---------------------------------------------------------------------------
// mma.sync / ldmatrix helpers (base sm_103 target — no 'a' features)
// ---------------------------------------------------------------------------
__device__ __forceinline__ uint32_t smem_u32(const void* p) {
    uint32_t a;
    asm("{ .reg .u64 t; cvta.to.shared.u64 t, %1; cvt.u32.u64 %0, t; }" : "=r"(a) : "l"(p));
    return a;
}
__device__ __forceinline__ void ldm_x4(uint32_t* r, uint32_t addr) {
    asm volatile("ldmatrix.sync.aligned.m8n8.x4.shared.b16 {%0,%1,%2,%3}, [%4];"
                 : "=r"(r[0]), "=r"(r[1]), "=r"(r[2]), "=r"(r[3]) : "r"(addr));
}
__device__ __forceinline__ void ldm_x2(uint32_t& r0, uint32_t& r1, uint32_t addr) {
    asm volatile("ldmatrix.sync.aligned.m8n8.x2.shared.b16 {%0,%1}, [%2];"
                 : "=r"(r0), "=r"(r1) : "r"(addr));
}
__device__ __forceinline__ void ldm_x2t(uint32_t& r0, uint32_t& r1, uint32_t addr) {
    asm volatile("ldmatrix.sync.aligned.m8n8.x2.trans.shared.b16 {%0,%1}, [%2];"
                 : "=r"(r0), "=r"(r1) : "r"(addr));
}
__device__ __forceinline__ void mma16816(float* c, const uint32_t* a, uint32_t b0, uint32_t b1) {
    asm volatile(
        "mma.sync.aligned.m16n8k16.row.col.f32.f16.f16.f32 "
        "{%0,%1,%2,%3}, {%4,%5,%6,%7}, {%8,%9}, {%0,%1,%2,%3};"
        : "+f"(c[0]), "+f"(c[1]), "+f"(c[2]), "+f"(c[3])
        : "r"(a[0]), "r"(a[1]), "r"(a[2]), "r"(a[3]), "r"(b0), "r"(b1));
}
__device__ __forceinline__ uint32_t packh2(float lo, float hi) {
    __half2 h = __float22half2_rn(make_float2(lo, hi));
    return *(uint32_t*)&h;
}
// swizzled byte offset of 16B unit u (0..15) in row r of a 64x128-half tile
__device__ __forceinline__ uint32_t swz(int r, int u) {
    return (uint32_t)(r * 256 + (((u & 8) | ((u ^ r) & 7)) << 4));
}

// ---------------------------------------------------------------------------
// inv_freq precompute in double
// ---------------------------------------------------------------------------
__global__ void invf_kernel() {
    int d = threadIdx.x;
    if (d < DH_N) g_invf[d] = pow(10000.0, -(double)d / 128.0);
}

// ---------------------------------------------------------------------------
// RoPE: read fp32 [T][nh*128], write fp16. pos = 6144 + t
// ---------------------------------------------------------------------------
__global__ void rope_h(const float* __restrict__ X, __half* __restrict__ Y, int nh) {
    int idx = blockIdx.x * blockDim.x + threadIdx.x;
    int total = T_LEN * nh * 64;
    if (idx >= total) return;
    int d = idx & 63;
    int h = (idx >> 6) % nh;
    int t = idx / (64 * nh);

    size_t base = (size_t)t * nh * DH_N + (size_t)h * DH_N;
    double pos = (double)(6144 + t);
    double f1 = pos * g_invf[d];
    double f2 = pos * g_invf[d + 64];
    const double inv2pi = 0.15915494309189535;
    const double twopi  = 6.283185307179586;
    f1 -= floor(f1 * inv2pi) * twopi;
    f2 -= floor(f2 * inv2pi) * twopi;
    float s1, c1, s2, c2;
    sincosf((float)f1, &s1, &c1);
    sincosf((float)f2, &s2, &c2);
    float x1 = X[base + d], x2 = X[base + d + 64];
    Y[base + d]      = __float2half_rn(x1 * c1 - x2 * s1);
    Y[base + d + 64] = __float2half_rn(x2 * c2 + x1 * s2);
}

// ---------------------------------------------------------------------------
// Generic fp32 GEMM (proven): C[M,N] = A[M,K] @ B[K,N]
// ---------------------------------------------------------------------------
__global__ void gemm64(const float* __restrict__ A, const float* __restrict__ B,
                       float* __restrict__ C, int M, int N, int K) {
    __shared__ float As[64][17];
    __shared__ float Bs[16][64];

    int tid = threadIdx.x;
    int tx = tid & 15, ty = tid >> 4;
    int m0 = blockIdx.y * 64, n0 = blockIdx.x * 64;

    int ar = tid >> 2,  ac = (tid & 3) << 2;
    int br = tid >> 4,  bc = (tid & 15) << 2;

    float acc[4][4];
#pragma unroll
    for (int i = 0; i < 4; i++)
#pragma unroll
        for (int j = 0; j < 4; j++) acc[i][j] = 0.f;

    int ty4 = ty << 2, tx4 = tx << 2;

    for (int k0 = 0; k0 < K; k0 += 16) {
        float4 a4 = *(const float4*)&A[(size_t)(m0 + ar) * K + k0 + ac];
        As[ar][ac + 0] = a4.x; As[ar][ac + 1] = a4.y;
        As[ar][ac + 2] = a4.z; As[ar][ac + 3] = a4.w;
        float4 b4 = *(const float4*)&B[(size_t)(k0 + br) * N + n0 + bc];
        *(float4*)&Bs[br][bc] = b4;
        __syncthreads();

#pragma unroll
        for (int kk = 0; kk < 16; kk++) {
            float a0 = As[ty4 + 0][kk];
            float a1 = As[ty4 + 1][kk];
            float a2 = As[ty4 + 2][kk];
            float a3 = As[ty4 + 3][kk];
            float4 b = *(const float4*)&Bs[kk][tx4];
            acc[0][0] += a0 * b.x; acc[0][1] += a0 * b.y; acc[0][2] += a0 * b.z; acc[0][3] += a0 * b.w;
            acc[1][0] += a1 * b.x; acc[1][1] += a1 * b.y; acc[1][2] += a1 * b.z; acc[1][3] += a1 * b.w;
            acc[2][0] += a2 * b.x; acc[2][1] += a2 * b.y; acc[2][2] += a2 * b.z; acc[2][3] += a2 * b.w;
            acc[3][0] += a3 * b.x; acc[3][1] += a3 * b.y; acc[3][2] += a3 * b.z; acc[3][3] += a3 * b.w;
        }
        __syncthreads();
    }

#pragma unroll
    for (int i = 0; i < 4; i++) {
        float4 r = make_float4(acc[i][0], acc[i][1], acc[i][2], acc[i][3]);
        *(float4*)&C[(size_t)(m0 + ty4 + i) * N + n0 + tx4] = r;
    }
}

// ---------------------------------------------------------------------------
// FA-2 attention on mma.sync fp16 (fp32 accum). Block = (64 q rows, head).
// 4 warps, each owns 16 query rows. Bc = 64 keys/tile, DH = 128.
// SMEM: sQ, sK, sV 64x128 half each (16KB), XOR-swizzled in 16B units.
// ---------------------------------------------------------------------------
#define ATTN_SMEM (3 * 64 * 128 * 2)

__global__ __launch_bounds__(128, 2)
void attn_mma(const __half* __restrict__ Qh, const __half* __restrict__ Kh,
              const __half* __restrict__ Vh, float* __restrict__ O) {
    extern __shared__ char smem[];
    char* sQb = smem;
    char* sKb = smem + 16384;
    char* sVb = smem + 32768;
    const uint32_t sQ_u = smem_u32(sQb);
    const uint32_t sK_u = smem_u32(sKb);
    const uint32_t sV_u = smem_u32(sVb);

    const int tid = threadIdx.x;
    const int w = tid >> 5, l = tid & 31;
    const int qt = blockIdx.x;      // 64-row query tile
    const int hq = blockIdx.y;      // query head
    const int g  = hq >> 2;         // kv head
    const float scale = 0.08838834764831845f;  // 1/sqrt(128)

    // Load Q tile [64][128] halves, swizzled. 1024 units / 128 threads = 8 each.
    {
        const __half* qg = Qh + (size_t)(qt * 64) * QDIM + hq * DH_N;
#pragma unroll
        for (int i = 0; i < 8; i++) {
            int idx = i * 128 + tid;
            int r = idx >> 4, u = idx & 15;
            *(uint4*)(sQb + swz(r, u)) = *(const uint4*)(qg + (size_t)r * QDIM + u * 8);
        }
    }
    __syncthreads();

    // Preload Q fragments: 8 k-steps of m16k16 per warp
    uint32_t qf[8][4];
    {
        int row = w * 16 + (l & 7) + ((l >> 3) & 1) * 8;
#pragma unroll
        for (int kk = 0; kk < 8; kk++) {
            int u = kk * 2 + (l >> 4);
            ldm_x4(qf[kk], sQ_u + swz(row, u));
        }
    }

    float o[16][4];
#pragma unroll
    for (int i = 0; i < 16; i++)
#pragma unroll
        for (int j = 0; j < 4; j++) o[i][j] = 0.f;
    float m0 = -FLT_MAX, m1 = -FLT_MAX, l0 = 0.f, l1 = 0.f;

    // ldmatrix lane-address components (lanes >=16 replicate lanes 0-15)
    const int kb_row = (l & 7);             // + nb*8 for K (non-trans)
    const int kb_uadd = (l >> 3) & 1;       // column half-select for K
    const int vb_row = (l & 7) + ((l >> 3) & 1) * 8;  // + kk2*16 for V (trans)

    for (int kb = 0; kb <= qt; kb++) {
        // Load K,V tiles [64][128] halves, swizzled
        {
            const __half* kg = Kh + (size_t)(kb * 64) * KDIM + g * DH_N;
            const __half* vg = Vh + (size_t)(kb * 64) * KDIM + g * DH_N;
#pragma unroll
            for (int i = 0; i < 8; i++) {
                int idx = i * 128 + tid;
                int r = idx >> 4, u = idx & 15;
                *(uint4*)(sKb + swz(r, u)) = *(const uint4*)(kg + (size_t)r * KDIM + u * 8);
                *(uint4*)(sVb + swz(r, u)) = *(const uint4*)(vg + (size_t)r * KDIM + u * 8);
            }
        }
        __syncthreads();

        // ---- S = Q @ K^T : c[nb] is a 16x8 tile, nb over 64 keys ----
        float c[8][4];
#pragma unroll
        for (int nb = 0; nb < 8; nb++)
#pragma unroll
            for (int j = 0; j < 4; j++) c[nb][j] = 0.f;

#pragma unroll
        for (int kk = 0; kk < 8; kk++) {
            int u = kk * 2 + kb_uadd;
#pragma unroll
            for (int nb = 0; nb < 8; nb++) {
                uint32_t b0, b1;
                ldm_x2(b0, b1, sK_u + swz(nb * 8 + kb_row, u));
                mma16816(c[nb], qf[kk], b0, b1);
            }
        }

        // ---- causal mask on diagonal tile ----
        if (kb == qt) {
            int r0 = w * 16 + (l >> 2), r1 = r0 + 8;
#pragma unroll
            for (int nb = 0; nb < 8; nb++) {
                int cb = nb * 8 + 2 * (l & 3);
                if (cb     > r0) c[nb][0] = -FLT_MAX;
                if (cb + 1 > r0) c[nb][1] = -FLT_MAX;
                if (cb     > r1) c[nb][2] = -FLT_MAX;
                if (cb + 1 > r1) c[nb][3] = -FLT_MAX;
            }
        }

        // ---- online softmax ----
        float mx0 = -FLT_MAX, mx1 = -FLT_MAX;
#pragma unroll
        for (int nb = 0; nb < 8; nb++) {
            mx0 = fmaxf(mx0, fmaxf(c[nb][0], c[nb][1]));
            mx1 = fmaxf(mx1, fmaxf(c[nb][2], c[nb][3]));
        }
        mx0 = fmaxf(mx0, __shfl_xor_sync(0xffffffffu, mx0, 1));
        mx0 = fmaxf(mx0, __shfl_xor_sync(0xffffffffu, mx0, 2));
        mx1 = fmaxf(mx1, __shfl_xor_sync(0xffffffffu, mx1, 1));
        mx1 = fmaxf(mx1, __shfl_xor_sync(0xffffffffu, mx1, 2));

        float mn0 = fmaxf(m0, mx0), mn1 = fmaxf(m1, mx1);
        float a0 = __expf((m0 - mn0) * scale);
        float a1 = __expf((m1 - mn1) * scale);
        m0 = mn0; m1 = mn1;
        l0 *= a0; l1 *= a1;

        float s0 = 0.f, s1 = 0.f;
#pragma unroll
        for (int nb = 0; nb < 8; nb++) {
            float p;
            p = __expf((c[nb][0] - m0) * scale); c[nb][0] = p; s0 += p;
            p = __expf((c[nb][1] - m0) * scale); c[nb][1] = p; s0 += p;
            p = __expf((c[nb][2] - m1) * scale); c[nb][2] = p; s1 += p;
            p = __expf((c[nb][3] - m1) * scale); c[nb][3] = p; s1 += p;
        }
        s0 += __shfl_xor_sync(0xffffffffu, s0, 1);
        s0 += __shfl_xor_sync(0xffffffffu, s0, 2);
        s1 += __shfl_xor_sync(0xffffffffu, s1, 1);
        s1 += __shfl_xor_sync(0xffffffffu, s1, 2);
        l0 += s0; l1 += s1;

        // rescale O
#pragma unroll
        for (int i = 0; i < 16; i++) {
            o[i][0] *= a0; o[i][1] *= a0;
            o[i][2] *= a1; o[i][3] *= a1;
        }

        // ---- pack P into A-fragments (4 key-chunks of 16) ----
        uint32_t pf[4][4];
#pragma unroll
        for (int k2 = 0; k2 < 4; k2++) {
            pf[k2][0] = packh2(c[2 * k2][0],     c[2 * k2][1]);
            pf[k2][1] = packh2(c[2 * k2][2],     c[2 * k2][3]);
            pf[k2][2] = packh2(c[2 * k2 + 1][0], c[2 * k2 + 1][1]);
            pf[k2][3] = packh2(c[2 * k2 + 1][2], c[2 * k2 + 1][3]);
        }

        // ---- O += P @ V ----
#pragma unroll
        for (int k2 = 0; k2 < 4; k2++) {
            int row = k2 * 16 + vb_row;
#pragma unroll
            for (int nb2 = 0; nb2 < 16; nb2++) {
                uint32_t b0, b1;
                ldm_x2t(b0, b1, sV_u + swz(row, nb2));
                mma16816(o[nb2], pf[k2], b0, b1);
            }
        }
        __syncthreads();   // protect sK/sV before next tile load
    }

    // ---- epilogue ----
    {
        float inv0 = 1.f / l0, inv1 = 1.f / l1;
        int gr0 = qt * 64 + w * 16 + (l >> 2), gr1 = gr0 + 8;
        float* ob0 = O + (size_t)gr0 * QDIM + hq * DH_N + 2 * (l & 3);
        float* ob1 = O + (size_t)gr1 * QDIM + hq * DH_N + 2 * (l & 3);
#pragma unroll
        for (int nb2 = 0; nb2 < 16; nb2++) {
            *(float2*)(ob0 + nb2 * 8) = make_float2(o[nb2][0] * inv0, o[nb2][1] * inv0);
            *(float2*)(ob1 + nb2 * 8) = make_float2(o[nb2][2] * inv1, o[nb2][3] * inv1);
        }
    }
}

// ---------------------------------------------------------------------------
// Launch
// ---------------------------------------------------------------------------
extern "C" void kernel_launch(void* const* d_in, const int* in_sizes, int n_in,
                              void* d_out, int out_size) {
    const float* q  = (const float*)d_in[0];
    const float* k  = (const float*)d_in[1];
    const float* v  = (const float*)d_in[2];
    // d_in[3] = mask (causal, reconstructed analytically)
    const float* Wq = (const float*)d_in[4];
    const float* Wk = (const float*)d_in[5];
    const float* Wv = (const float*)d_in[6];
    const float* Wo = (const float*)d_in[7];
    float* out = (float*)d_out;

    float *Qb, *Kb, *Vb, *Ob;
    __half *Qh, *Kh, *Vh;
    cudaGetSymbolAddress((void**)&Qb, g_Q);
    cudaGetSymbolAddress((void**)&Kb, g_K);
    cudaGetSymbolAddress((void**)&Vb, g_V);
    cudaGetSymbolAddress((void**)&Qh, g_Qh);
    cudaGetSymbolAddress((void**)&Kh, g_Kh);
    cudaGetSymbolAddress((void**)&Vh, g_Vh);
    cudaGetSymbolAddress((void**)&Ob, g_O);

    cudaFuncSetAttribute(attn_mma, cudaFuncAttributeMaxDynamicSharedMemorySize, ATTN_SMEM);

    invf_kernel<<<1, 128>>>();

    gemm64<<<dim3(QDIM / 64, T_LEN / 64), 256>>>(q, Wq, Qb, T_LEN, QDIM, DIMM);
    gemm64<<<dim3(KDIM / 64, T_LEN / 64), 256>>>(k, Wk, Kb, T_LEN, KDIM, DIMM);
    gemm64<<<dim3(KDIM / 64, T_LEN / 64), 256>>>(v, Wv, Vb, T_LEN, KDIM, DIMM);

    rope_h<<<(T_LEN * HQ_N * 64 + 255) / 256, 256>>>(Qb, Qh, HQ_N);
    rope_h<<<(T_LEN * HK_N * 64 + 255) / 256, 256>>>(Kb, Kh, HK_N);
    rope_h<<<(T_LEN * HK_N * 64 + 255) / 256, 256>>>(Vb, Vh, HK_N);

    attn_mma<<<dim3(T_LEN / 64, HQ_N), 128, ATTN_SMEM>>>(Qh, Kh, Vh, Ob);

    gemm64<<<dim3(DIMM / 64, T_LEN / 64), 256>>>(Ob, Wo, out, T_LEN, DIMM, QDIM);
}

// round 4
// speedup vs baseline: 5.3074x; 1.8940x over previous
#include <cuda_runtime.h>
#include <cuda_fp16.h>
#include <math.h>
#include <float.h>
#include <stdint.h>

// ---------------------------------------------------------------------------
// Problem constants
// ---------------------------------------------------------------------------
#define T_LEN 2048
#define DIMM  256
#define HQ_N  32
#define HK_N  8
#define DH_N  128
#define QDIM  (HQ_N * DH_N)   // 4096
#define KDIM  (HK_N * DH_N)   // 1024

// Scratch (no cudaMalloc allowed)
__device__ __align__(16) float  g_Q[T_LEN * QDIM];     // Q proj out (fp32, pre-rope)
__device__ __align__(16) float  g_K[T_LEN * KDIM];
__device__ __align__(16) float  g_V[T_LEN * KDIM];
__device__ __align__(16) __half g_Qh[T_LEN * QDIM];    // post-rope fp16
__device__ __align__(16) __half g_Kh[T_LEN * KDIM];
__device__ __align__(16) __half g_Vh[T_LEN * KDIM];
__device__ __align__(16) __half g_Oh[T_LEN * QDIM];    // attention out fp16
__device__ __align__(16) __half g_xq[T_LEN * DIMM];    // fp16 inputs
__device__ __align__(16) __half g_xk[T_LEN * DIMM];
__device__ __align__(16) __half g_xv[T_LEN * DIMM];
__device__ __align__(16) __half g_Wqt[QDIM * DIMM];    // W^T fp16 [N][K]
__device__ __align__(16) __half g_Wkt[KDIM * DIMM];
__device__ __align__(16) __half g_Wvt[KDIM * DIMM];
__device__ __align__(16) __half g_Wot[DIMM * QDIM];
__device__ __align__(16) float  g_part[4 * T_LEN * DIMM];  // split-K partials
__device__ double g_invf[DH_N];

// ---------------------------------------------------------------------------
// mma.sync / ldmatrix helpers (base sm_103 target)
// ---------------------------------------------------------------------------
__device__ __forceinline__ uint32_t smem_u32(const void* p) {
    uint32_t a;
    asm("{ .reg .u64 t; cvta.to.shared.u64 t, %1; cvt.u32.u64 %0, t; }" : "=r"(a) : "l"(p));
    return a;
}
__device__ __forceinline__ void ldm_x4(uint32_t* r, uint32_t addr) {
    asm volatile("ldmatrix.sync.aligned.m8n8.x4.shared.b16 {%0,%1,%2,%3}, [%4];"
                 : "=r"(r[0]), "=r"(r[1]), "=r"(r[2]), "=r"(r[3]) : "r"(addr));
}
__device__ __forceinline__ void ldm_x2(uint32_t& r0, uint32_t& r1, uint32_t addr) {
    asm volatile("ldmatrix.sync.aligned.m8n8.x2.shared.b16 {%0,%1}, [%2];"
                 : "=r"(r0), "=r"(r1) : "r"(addr));
}
__device__ __forceinline__ void ldm_x2t(uint32_t& r0, uint32_t& r1, uint32_t addr) {
    asm volatile("ldmatrix.sync.aligned.m8n8.x2.trans.shared.b16 {%0,%1}, [%2];"
                 : "=r"(r0), "=r"(r1) : "r"(addr));
}
__device__ __forceinline__ void mma16816(float* c, const uint32_t* a, uint32_t b0, uint32_t b1) {
    asm volatile(
        "mma.sync.aligned.m16n8k16.row.col.f32.f16.f16.f32 "
        "{%0,%1,%2,%3}, {%4,%5,%6,%7}, {%8,%9}, {%0,%1,%2,%3};"
        : "+f"(c[0]), "+f"(c[1]), "+f"(c[2]), "+f"(c[3])
        : "r"(a[0]), "r"(a[1]), "r"(a[2]), "r"(a[3]), "r"(b0), "r"(b1));
}
__device__ __forceinline__ uint32_t packh2(float lo, float hi) {
    __half2 h = __float22half2_rn(make_float2(lo, hi));
    return *(uint32_t*)&h;
}
// swizzled byte offset, 128-half (256B) rows, 16B units u in [0,16)
__device__ __forceinline__ uint32_t swz(int r, int u) {
    return (uint32_t)(r * 256 + (((u & 8) | ((u ^ r) & 7)) << 4));
}
// swizzled byte offset, 64-half (128B) rows, units u in [0,8)
__device__ __forceinline__ uint32_t swz64(int r, int u) {
    return (uint32_t)(r * 128 + (((u ^ r) & 7) << 4));
}

// ---------------------------------------------------------------------------
// Prep kernels
// ---------------------------------------------------------------------------
__global__ void invf_kernel() {
    int d = threadIdx.x;
    if (d < DH_N) g_invf[d] = pow(10000.0, -(double)d / 128.0);
}

__global__ void f2h_kernel(const float* __restrict__ X, __half* __restrict__ Y, int n) {
    int i = blockIdx.x * blockDim.x + threadIdx.x;
    if (i * 4 >= n) return;
    float4 v = *(const float4*)(X + i * 4);
    __half2 a = __float22half2_rn(make_float2(v.x, v.y));
    __half2 b = __float22half2_rn(make_float2(v.z, v.w));
    *(uint32_t*)(Y + i * 4)     = *(uint32_t*)&a;
    *(uint32_t*)(Y + i * 4 + 2) = *(uint32_t*)&b;
}

// Wt[n][k] = (half)W[k][n];  W is [K][N] fp32
__global__ void tcast_kernel(const float* __restrict__ W, __half* __restrict__ Wt,
                             int K, int N) {
    __shared__ float t[32][33];
    int n0 = blockIdx.x * 32, k0 = blockIdx.y * 32;
    int tx = threadIdx.x, ty = threadIdx.y;
    t[ty][tx] = W[(size_t)(k0 + ty) * N + n0 + tx];
    __syncthreads();
    Wt[(size_t)(n0 + ty) * K + k0 + tx] = __float2half_rn(t[tx][ty]);
}

// ---------------------------------------------------------------------------
// RoPE: read fp32 [T][nh*128], write fp16. pos = 6144 + t
// ---------------------------------------------------------------------------
__global__ void rope_h(const float* __restrict__ X, __half* __restrict__ Y, int nh) {
    int idx = blockIdx.x * blockDim.x + threadIdx.x;
    int total = T_LEN * nh * 64;
    if (idx >= total) return;
    int d = idx & 63;
    int h = (idx >> 6) % nh;
    int t = idx / (64 * nh);

    size_t base = (size_t)t * nh * DH_N + (size_t)h * DH_N;
    double pos = (double)(6144 + t);
    double f1 = pos * g_invf[d];
    double f2 = pos * g_invf[d + 64];
    const double inv2pi = 0.15915494309189535;
    const double twopi  = 6.283185307179586;
    f1 -= floor(f1 * inv2pi) * twopi;
    f2 -= floor(f2 * inv2pi) * twopi;
    float s1, c1, s2, c2;
    sincosf((float)f1, &s1, &c1);
    sincosf((float)f2, &s2, &c2);
    float x1 = X[base + d], x2 = X[base + d + 64];
    Y[base + d]      = __float2half_rn(x1 * c1 - x2 * s1);
    Y[base + d + 64] = __float2half_rn(x2 * c2 + x1 * s2);
}

// ---------------------------------------------------------------------------
// fp16 tensor-core GEMM: C[M,N] = A[M,K] * Bt[N,K]^T, fp32 accum/out.
// 128x128 tile, BK=64, 256 threads (8 warps as 4m x 2n, warp tile 32x64).
// blockIdx.z selects a K-split of length klen; C advanced by z*M*N.
// ---------------------------------------------------------------------------
__global__ __launch_bounds__(256, 2)
void hgemm(const __half* __restrict__ A, const __half* __restrict__ Bt,
           float* __restrict__ C, int M, int N, int K, int klen) {
    __shared__ __align__(16) __half sA[128 * 64];
    __shared__ __align__(16) __half sB[128 * 64];
    const uint32_t sA_u = smem_u32(sA);
    const uint32_t sB_u = smem_u32(sB);

    const int tid = threadIdx.x;
    const int w = tid >> 5, l = tid & 31;
    const int wm = w >> 1, wn = w & 1;
    const int m0 = blockIdx.y * 128, n0 = blockIdx.x * 128;
    const int kstart = blockIdx.z * klen;
    C += (size_t)blockIdx.z * M * N;

    float c[2][8][4];
#pragma unroll
    for (int mi = 0; mi < 2; mi++)
#pragma unroll
        for (int nb = 0; nb < 8; nb++)
#pragma unroll
            for (int j = 0; j < 4; j++) c[mi][nb][j] = 0.f;

    const int lr = tid >> 3, lu = tid & 7;        // tile loads: 1024 units/256 thr
    const int arow = wm * 32 + (l & 7) + ((l >> 3) & 1) * 8;
    const int au = (l >> 4);
    const int brow = wn * 64 + (l & 7);
    const int bu = (l >> 3) & 1;

    for (int kc = 0; kc < klen; kc += 64) {
        const __half* Ab = A + (size_t)m0 * K + kstart + kc;
        const __half* Bb = Bt + (size_t)n0 * K + kstart + kc;
#pragma unroll
        for (int i = 0; i < 4; i++) {
            int r = i * 32 + lr;
            *(uint4*)((char*)sA + swz64(r, lu)) = *(const uint4*)(Ab + (size_t)r * K + lu * 8);
            *(uint4*)((char*)sB + swz64(r, lu)) = *(const uint4*)(Bb + (size_t)r * K + lu * 8);
        }
        __syncthreads();

#pragma unroll
        for (int kk = 0; kk < 4; kk++) {
            uint32_t af0[4], af1[4];
            ldm_x4(af0, sA_u + swz64(arow,      kk * 2 + au));
            ldm_x4(af1, sA_u + swz64(arow + 16, kk * 2 + au));
#pragma unroll
            for (int nb = 0; nb < 8; nb++) {
                uint32_t b0, b1;
                ldm_x2(b0, b1, sB_u + swz64(brow + nb * 8, kk * 2 + bu));
                mma16816(c[0][nb], af0, b0, b1);
                mma16816(c[1][nb], af1, b0, b1);
            }
        }
        __syncthreads();
    }

#pragma unroll
    for (int mi = 0; mi < 2; mi++) {
        int gr = m0 + wm * 32 + mi * 16 + (l >> 2);
#pragma unroll
        for (int nb = 0; nb < 8; nb++) {
            int gc = n0 + wn * 64 + nb * 8 + 2 * (l & 3);
            *(float2*)(C + (size_t)gr * N + gc)       = make_float2(c[mi][nb][0], c[mi][nb][1]);
            *(float2*)(C + (size_t)(gr + 8) * N + gc) = make_float2(c[mi][nb][2], c[mi][nb][3]);
        }
    }
}

// sum 4 split-K partials into out
__global__ void reduce4_kernel(const float* __restrict__ P, float* __restrict__ out, int n) {
    int i = blockIdx.x * blockDim.x + threadIdx.x;
    if (i * 4 >= n) return;
    float4 a = *(const float4*)(P + i * 4);
    float4 b = *(const float4*)(P + n + i * 4);
    float4 cc = *(const float4*)(P + 2 * n + i * 4);
    float4 d = *(const float4*)(P + 3 * n + i * 4);
    float4 r = make_float4(a.x + b.x + cc.x + d.x, a.y + b.y + cc.y + d.y,
                           a.z + b.z + cc.z + d.z, a.w + b.w + cc.w + d.w);
    *(float4*)(out + i * 4) = r;
}

// ---------------------------------------------------------------------------
// FA-2 attention on mma.sync fp16 (fp32 accum). Block = (64 q rows, head).
// ---------------------------------------------------------------------------
#define ATTN_SMEM (3 * 64 * 128 * 2)

__global__ __launch_bounds__(128, 2)
void attn_mma(const __half* __restrict__ Qh, const __half* __restrict__ Kh,
              const __half* __restrict__ Vh, __half* __restrict__ O) {
    extern __shared__ char smem[];
    char* sQb = smem;
    char* sKb = smem + 16384;
    char* sVb = smem + 32768;
    const uint32_t sQ_u = smem_u32(sQb);
    const uint32_t sK_u = smem_u32(sKb);
    const uint32_t sV_u = smem_u32(sVb);

    const int tid = threadIdx.x;
    const int w = tid >> 5, l = tid & 31;
    const int qt = blockIdx.x;
    const int hq = blockIdx.y;
    const int g  = hq >> 2;
    const float scale = 0.08838834764831845f;

    {
        const __half* qg = Qh + (size_t)(qt * 64) * QDIM + hq * DH_N;
#pragma unroll
        for (int i = 0; i < 8; i++) {
            int idx = i * 128 + tid;
            int r = idx >> 4, u = idx & 15;
            *(uint4*)(sQb + swz(r, u)) = *(const uint4*)(qg + (size_t)r * QDIM + u * 8);
        }
    }
    __syncthreads();

    uint32_t qf[8][4];
    {
        int row = w * 16 + (l & 7) + ((l >> 3) & 1) * 8;
#pragma unroll
        for (int kk = 0; kk < 8; kk++) {
            int u = kk * 2 + (l >> 4);
            ldm_x4(qf[kk], sQ_u + swz(row, u));
        }
    }

    float o[16][4];
#pragma unroll
    for (int i = 0; i < 16; i++)
#pragma unroll
        for (int j = 0; j < 4; j++) o[i][j] = 0.f;
    float m0 = -FLT_MAX, m1 = -FLT_MAX, l0 = 0.f, l1 = 0.f;

    const int kb_row = (l & 7);
    const int kb_uadd = (l >> 3) & 1;
    const int vb_row = (l & 7) + ((l >> 3) & 1) * 8;

    for (int kb = 0; kb <= qt; kb++) {
        {
            const __half* kg = Kh + (size_t)(kb * 64) * KDIM + g * DH_N;
            const __half* vg = Vh + (size_t)(kb * 64) * KDIM + g * DH_N;
#pragma unroll
            for (int i = 0; i < 8; i++) {
                int idx = i * 128 + tid;
                int r = idx >> 4, u = idx & 15;
                *(uint4*)(sKb + swz(r, u)) = *(const uint4*)(kg + (size_t)r * KDIM + u * 8);
                *(uint4*)(sVb + swz(r, u)) = *(const uint4*)(vg + (size_t)r * KDIM + u * 8);
            }
        }
        __syncthreads();

        float c[8][4];
#pragma unroll
        for (int nb = 0; nb < 8; nb++)
#pragma unroll
            for (int j = 0; j < 4; j++) c[nb][j] = 0.f;

#pragma unroll
        for (int kk = 0; kk < 8; kk++) {
            int u = kk * 2 + kb_uadd;
#pragma unroll
            for (int nb = 0; nb < 8; nb++) {
                uint32_t b0, b1;
                ldm_x2(b0, b1, sK_u + swz(nb * 8 + kb_row, u));
                mma16816(c[nb], qf[kk], b0, b1);
            }
        }

        if (kb == qt) {
            int r0 = w * 16 + (l >> 2), r1 = r0 + 8;
#pragma unroll
            for (int nb = 0; nb < 8; nb++) {
                int cb = nb * 8 + 2 * (l & 3);
                if (cb     > r0) c[nb][0] = -FLT_MAX;
                if (cb + 1 > r0) c[nb][1] = -FLT_MAX;
                if (cb     > r1) c[nb][2] = -FLT_MAX;
                if (cb + 1 > r1) c[nb][3] = -FLT_MAX;
            }
        }

        float mx0 = -FLT_MAX, mx1 = -FLT_MAX;
#pragma unroll
        for (int nb = 0; nb < 8; nb++) {
            mx0 = fmaxf(mx0, fmaxf(c[nb][0], c[nb][1]));
            mx1 = fmaxf(mx1, fmaxf(c[nb][2], c[nb][3]));
        }
        mx0 = fmaxf(mx0, __shfl_xor_sync(0xffffffffu, mx0, 1));
        mx0 = fmaxf(mx0, __shfl_xor_sync(0xffffffffu, mx0, 2));
        mx1 = fmaxf(mx1, __shfl_xor_sync(0xffffffffu, mx1, 1));
        mx1 = fmaxf(mx1, __shfl_xor_sync(0xffffffffu, mx1, 2));

        float mn0 = fmaxf(m0, mx0), mn1 = fmaxf(m1, mx1);
        float a0 = __expf((m0 - mn0) * scale);
        float a1 = __expf((m1 - mn1) * scale);
        m0 = mn0; m1 = mn1;
        l0 *= a0; l1 *= a1;

        float s0 = 0.f, s1 = 0.f;
#pragma unroll
        for (int nb = 0; nb < 8; nb++) {
            float p;
            p = __expf((c[nb][0] - m0) * scale); c[nb][0] = p; s0 += p;
            p = __expf((c[nb][1] - m0) * scale); c[nb][1] = p; s0 += p;
            p = __expf((c[nb][2] - m1) * scale); c[nb][2] = p; s1 += p;
            p = __expf((c[nb][3] - m1) * scale); c[nb][3] = p; s1 += p;
        }
        s0 += __shfl_xor_sync(0xffffffffu, s0, 1);
        s0 += __shfl_xor_sync(0xffffffffu, s0, 2);
        s1 += __shfl_xor_sync(0xffffffffu, s1, 1);
        s1 += __shfl_xor_sync(0xffffffffu, s1, 2);
        l0 += s0; l1 += s1;

#pragma unroll
        for (int i = 0; i < 16; i++) {
            o[i][0] *= a0; o[i][1] *= a0;
            o[i][2] *= a1; o[i][3] *= a1;
        }

        uint32_t pf[4][4];
#pragma unroll
        for (int k2 = 0; k2 < 4; k2++) {
            pf[k2][0] = packh2(c[2 * k2][0],     c[2 * k2][1]);
            pf[k2][1] = packh2(c[2 * k2][2],     c[2 * k2][3]);
            pf[k2][2] = packh2(c[2 * k2 + 1][0], c[2 * k2 + 1][1]);
            pf[k2][3] = packh2(c[2 * k2 + 1][2], c[2 * k2 + 1][3]);
        }

#pragma unroll
        for (int k2 = 0; k2 < 4; k2++) {
            int row = k2 * 16 + vb_row;
#pragma unroll
            for (int nb2 = 0; nb2 < 16; nb2++) {
                uint32_t b0, b1;
                ldm_x2t(b0, b1, sV_u + swz(row, nb2));
                mma16816(o[nb2], pf[k2], b0, b1);
            }
        }
        __syncthreads();
    }

    // epilogue: write fp16 O (feeds the output projection)
    {
        float inv0 = 1.f / l0, inv1 = 1.f / l1;
        int gr0 = qt * 64 + w * 16 + (l >> 2), gr1 = gr0 + 8;
        __half* ob0 = O + (size_t)gr0 * QDIM + hq * DH_N + 2 * (l & 3);
        __half* ob1 = O + (size_t)gr1 * QDIM + hq * DH_N + 2 * (l & 3);
#pragma unroll
        for (int nb2 = 0; nb2 < 16; nb2++) {
            uint32_t p0 = packh2(o[nb2][0] * inv0, o[nb2][1] * inv0);
            uint32_t p1 = packh2(o[nb2][2] * inv1, o[nb2][3] * inv1);
            *(uint32_t*)(ob0 + nb2 * 8) = p0;
            *(uint32_t*)(ob1 + nb2 * 8) = p1;
        }
    }
}

// ---------------------------------------------------------------------------
// Launch
// ---------------------------------------------------------------------------
extern "C" void kernel_launch(void* const* d_in, const int* in_sizes, int n_in,
                              void* d_out, int out_size) {
    const float* q  = (const float*)d_in[0];
    const float* k  = (const float*)d_in[1];
    const float* v  = (const float*)d_in[2];
    // d_in[3] = mask (causal, reconstructed analytically)
    const float* Wq = (const float*)d_in[4];
    const float* Wk = (const float*)d_in[5];
    const float* Wv = (const float*)d_in[6];
    const float* Wo = (const float*)d_in[7];
    float* out = (float*)d_out;

    float *Qb, *Kb, *Vb, *Part;
    __half *Qh, *Kh, *Vh, *Oh, *xq, *xk, *xv, *Wqt, *Wkt, *Wvt, *Wot;
    cudaGetSymbolAddress((void**)&Qb, g_Q);
    cudaGetSymbolAddress((void**)&Kb, g_K);
    cudaGetSymbolAddress((void**)&Vb, g_V);
    cudaGetSymbolAddress((void**)&Qh, g_Qh);
    cudaGetSymbolAddress((void**)&Kh, g_Kh);
    cudaGetSymbolAddress((void**)&Vh, g_Vh);
    cudaGetSymbolAddress((void**)&Oh, g_Oh);
    cudaGetSymbolAddress((void**)&xq, g_xq);
    cudaGetSymbolAddress((void**)&xk, g_xk);
    cudaGetSymbolAddress((void**)&xv, g_xv);
    cudaGetSymbolAddress((void**)&Wqt, g_Wqt);
    cudaGetSymbolAddress((void**)&Wkt, g_Wkt);
    cudaGetSymbolAddress((void**)&Wvt, g_Wvt);
    cudaGetSymbolAddress((void**)&Wot, g_Wot);
    cudaGetSymbolAddress((void**)&Part, g_part);

    cudaFuncSetAttribute(attn_mma, cudaFuncAttributeMaxDynamicSharedMemorySize, ATTN_SMEM);

    invf_kernel<<<1, 128>>>();

    // casts + weight transposes
    int nin = T_LEN * DIMM;
    f2h_kernel<<<(nin / 4 + 255) / 256, 256>>>(q, xq, nin);
    f2h_kernel<<<(nin / 4 + 255) / 256, 256>>>(k, xk, nin);
    f2h_kernel<<<(nin / 4 + 255) / 256, 256>>>(v, xv, nin);
    tcast_kernel<<<dim3(QDIM / 32, DIMM / 32), dim3(32, 32)>>>(Wq, Wqt, DIMM, QDIM);
    tcast_kernel<<<dim3(KDIM / 32, DIMM / 32), dim3(32, 32)>>>(Wk, Wkt, DIMM, KDIM);
    tcast_kernel<<<dim3(KDIM / 32, DIMM / 32), dim3(32, 32)>>>(Wv, Wvt, DIMM, KDIM);
    tcast_kernel<<<dim3(DIMM / 32, QDIM / 32), dim3(32, 32)>>>(Wo, Wot, QDIM, DIMM);

    // projections (tensor cores)
    hgemm<<<dim3(QDIM / 128, T_LEN / 128, 1), 256>>>(xq, Wqt, Qb, T_LEN, QDIM, DIMM, DIMM);
    hgemm<<<dim3(KDIM / 128, T_LEN / 128, 1), 256>>>(xk, Wkt, Kb, T_LEN, KDIM, DIMM, DIMM);
    hgemm<<<dim3(KDIM / 128, T_LEN / 128, 1), 256>>>(xv, Wvt, Vb, T_LEN, KDIM, DIMM, DIMM);

    // RoPE -> fp16
    rope_h<<<(T_LEN * HQ_N * 64 + 255) / 256, 256>>>(Qb, Qh, HQ_N);
    rope_h<<<(T_LEN * HK_N * 64 + 255) / 256, 256>>>(Kb, Kh, HK_N);
    rope_h<<<(T_LEN * HK_N * 64 + 255) / 256, 256>>>(Vb, Vh, HK_N);

    // attention
    attn_mma<<<dim3(T_LEN / 64, HQ_N), 128, ATTN_SMEM>>>(Qh, Kh, Vh, Oh);

    // output projection: split-K=4 into partials, then reduce
    hgemm<<<dim3(DIMM / 128, T_LEN / 128, 4), 256>>>(Oh, Wot, Part, T_LEN, DIMM, QDIM, QDIM / 4);
    reduce4_kernel<<<(T_LEN * DIMM / 4 + 255) / 256, 256>>>(Part, out, T_LEN * DIMM);
}

// round 5
// speedup vs baseline: 5.6085x; 1.0567x over previous
#include <cuda_runtime.h>
#include <cuda_fp16.h>
#include <math.h>
#include <float.h>
#include <stdint.h>

// ---------------------------------------------------------------------------
// Problem constants
// ---------------------------------------------------------------------------
#define T_LEN 2048
#define DIMM  256
#define HQ_N  32
#define HK_N  8
#define DH_N  128
#define QDIM  (HQ_N * DH_N)   // 4096
#define KDIM  (HK_N * DH_N)   // 1024

// scale/log2e fold for softmax-via-ex2
#define Q_PREMUL (0.08838834764831845 * 1.4426950408889634)

// Scratch (no cudaMalloc allowed)
__device__ __align__(16) float  g_Q[T_LEN * QDIM];
__device__ __align__(16) float  g_K[T_LEN * KDIM];
__device__ __align__(16) float  g_V[T_LEN * KDIM];
__device__ __align__(16) __half g_Qh[T_LEN * QDIM];
__device__ __align__(16) __half g_Kh[T_LEN * KDIM];
__device__ __align__(16) __half g_Vh[T_LEN * KDIM];
__device__ __align__(16) __half g_Oh[T_LEN * QDIM];
__device__ __align__(16) __half g_xq[T_LEN * DIMM];
__device__ __align__(16) __half g_xk[T_LEN * DIMM];
__device__ __align__(16) __half g_xv[T_LEN * DIMM];
__device__ __align__(16) __half g_Wqt[QDIM * DIMM];
__device__ __align__(16) __half g_Wkt[KDIM * DIMM];
__device__ __align__(16) __half g_Wvt[KDIM * DIMM];
__device__ __align__(16) __half g_Wot[DIMM * QDIM];
__device__ __align__(16) float  g_part[4 * T_LEN * DIMM];
__device__ double g_invf[DH_N];

// ---------------------------------------------------------------------------
// PTX helpers
// ---------------------------------------------------------------------------
__device__ __forceinline__ uint32_t smem_u32(const void* p) {
    uint32_t a;
    asm("{ .reg .u64 t; cvta.to.shared.u64 t, %1; cvt.u32.u64 %0, t; }" : "=r"(a) : "l"(p));
    return a;
}
__device__ __forceinline__ void ldm_x4(uint32_t* r, uint32_t addr) {
    asm volatile("ldmatrix.sync.aligned.m8n8.x4.shared.b16 {%0,%1,%2,%3}, [%4];"
                 : "=r"(r[0]), "=r"(r[1]), "=r"(r[2]), "=r"(r[3]) : "r"(addr));
}
__device__ __forceinline__ void ldm_x2(uint32_t& r0, uint32_t& r1, uint32_t addr) {
    asm volatile("ldmatrix.sync.aligned.m8n8.x2.shared.b16 {%0,%1}, [%2];"
                 : "=r"(r0), "=r"(r1) : "r"(addr));
}
__device__ __forceinline__ void ldm_x4t(uint32_t* r, uint32_t addr) {
    asm volatile("ldmatrix.sync.aligned.m8n8.x4.trans.shared.b16 {%0,%1,%2,%3}, [%4];"
                 : "=r"(r[0]), "=r"(r[1]), "=r"(r[2]), "=r"(r[3]) : "r"(addr));
}
__device__ __forceinline__ void mma16816(float* c, const uint32_t* a, uint32_t b0, uint32_t b1) {
    asm volatile(
        "mma.sync.aligned.m16n8k16.row.col.f32.f16.f16.f32 "
        "{%0,%1,%2,%3}, {%4,%5,%6,%7}, {%8,%9}, {%0,%1,%2,%3};"
        : "+f"(c[0]), "+f"(c[1]), "+f"(c[2]), "+f"(c[3])
        : "r"(a[0]), "r"(a[1]), "r"(a[2]), "r"(a[3]), "r"(b0), "r"(b1));
}
__device__ __forceinline__ uint32_t packh2(float lo, float hi) {
    __half2 h = __float22half2_rn(make_float2(lo, hi));
    return *(uint32_t*)&h;
}
__device__ __forceinline__ float fast_ex2(float x) {
    float y;
    asm("ex2.approx.ftz.f32 %0, %1;" : "=f"(y) : "f"(x));
    return y;
}
__device__ __forceinline__ void cp16(uint32_t saddr, const void* g) {
    asm volatile("cp.async.cg.shared.global [%0], [%1], 16;" :: "r"(saddr), "l"(g));
}
#define CP_COMMIT() asm volatile("cp.async.commit_group;" ::: "memory")
#define CP_WAIT(n)  asm volatile("cp.async.wait_group %0;" :: "n"(n) : "memory")

// swizzled byte offset, 128-half (256B) rows, 16B units u in [0,16)
__device__ __forceinline__ uint32_t swz(int r, int u) {
    return (uint32_t)(r * 256 + (((u & 8) | ((u ^ r) & 7)) << 4));
}
// swizzled byte offset, 64-half (128B) rows, units u in [0,8)
__device__ __forceinline__ uint32_t swz64(int r, int u) {
    return (uint32_t)(r * 128 + (((u ^ r) & 7) << 4));
}

// ---------------------------------------------------------------------------
// Prep kernels
// ---------------------------------------------------------------------------
__global__ void invf_kernel() {
    int d = threadIdx.x;
    if (d < DH_N) g_invf[d] = pow(10000.0, -(double)d / 128.0);
}

__global__ void f2h_kernel(const float* __restrict__ X, __half* __restrict__ Y, int n) {
    int i = blockIdx.x * blockDim.x + threadIdx.x;
    if (i * 4 >= n) return;
    float4 v = *(const float4*)(X + i * 4);
    __half2 a = __float22half2_rn(make_float2(v.x, v.y));
    __half2 b = __float22half2_rn(make_float2(v.z, v.w));
    *(uint32_t*)(Y + i * 4)     = *(uint32_t*)&a;
    *(uint32_t*)(Y + i * 4 + 2) = *(uint32_t*)&b;
}

// Wt[n][k] = (half)W[k][n];  W is [K][N] fp32
__global__ void tcast_kernel(const float* __restrict__ W, __half* __restrict__ Wt,
                             int K, int N) {
    __shared__ float t[32][33];
    int n0 = blockIdx.x * 32, k0 = blockIdx.y * 32;
    int tx = threadIdx.x, ty = threadIdx.y;
    t[ty][tx] = W[(size_t)(k0 + ty) * N + n0 + tx];
    __syncthreads();
    Wt[(size_t)(n0 + ty) * K + k0 + tx] = __float2half_rn(t[tx][ty]);
}

// ---------------------------------------------------------------------------
// RoPE: read fp32 [T][nh*128], write fp16 scaled by `mult`. pos = 6144 + t
// ---------------------------------------------------------------------------
__global__ void rope_h(const float* __restrict__ X, __half* __restrict__ Y, int nh,
                       float mult) {
    int idx = blockIdx.x * blockDim.x + threadIdx.x;
    int total = T_LEN * nh * 64;
    if (idx >= total) return;
    int d = idx & 63;
    int h = (idx >> 6) % nh;
    int t = idx / (64 * nh);

    size_t base = (size_t)t * nh * DH_N + (size_t)h * DH_N;
    double pos = (double)(6144 + t);
    double f1 = pos * g_invf[d];
    double f2 = pos * g_invf[d + 64];
    const double inv2pi = 0.15915494309189535;
    const double twopi  = 6.283185307179586;
    f1 -= floor(f1 * inv2pi) * twopi;
    f2 -= floor(f2 * inv2pi) * twopi;
    float s1, c1, s2, c2;
    sincosf((float)f1, &s1, &c1);
    sincosf((float)f2, &s2, &c2);
    float x1 = X[base + d], x2 = X[base + d + 64];
    Y[base + d]      = __float2half_rn((x1 * c1 - x2 * s1) * mult);
    Y[base + d + 64] = __float2half_rn((x2 * c2 + x1 * s2) * mult);
}

// ---------------------------------------------------------------------------
// fp16 tensor-core GEMM: C[M,N] = A[M,K] * Bt[N,K]^T, fp32 accum/out.
// ---------------------------------------------------------------------------
__global__ __launch_bounds__(256, 2)
void hgemm(const __half* __restrict__ A, const __half* __restrict__ Bt,
           float* __restrict__ C, int M, int N, int K, int klen) {
    __shared__ __align__(16) __half sA[128 * 64];
    __shared__ __align__(16) __half sB[128 * 64];
    const uint32_t sA_u = smem_u32(sA);
    const uint32_t sB_u = smem_u32(sB);

    const int tid = threadIdx.x;
    const int w = tid >> 5, l = tid & 31;
    const int wm = w >> 1, wn = w & 1;
    const int m0 = blockIdx.y * 128, n0 = blockIdx.x * 128;
    const int kstart = blockIdx.z * klen;
    C += (size_t)blockIdx.z * M * N;

    float c[2][8][4];
#pragma unroll
    for (int mi = 0; mi < 2; mi++)
#pragma unroll
        for (int nb = 0; nb < 8; nb++)
#pragma unroll
            for (int j = 0; j < 4; j++) c[mi][nb][j] = 0.f;

    const int lr = tid >> 3, lu = tid & 7;
    const int arow = wm * 32 + (l & 7) + ((l >> 3) & 1) * 8;
    const int au = (l >> 4);
    const int brow = wn * 64 + (l & 7);
    const int bu = (l >> 3) & 1;

    for (int kc = 0; kc < klen; kc += 64) {
        const __half* Ab = A + (size_t)m0 * K + kstart + kc;
        const __half* Bb = Bt + (size_t)n0 * K + kstart + kc;
#pragma unroll
        for (int i = 0; i < 4; i++) {
            int r = i * 32 + lr;
            *(uint4*)((char*)sA + swz64(r, lu)) = *(const uint4*)(Ab + (size_t)r * K + lu * 8);
            *(uint4*)((char*)sB + swz64(r, lu)) = *(const uint4*)(Bb + (size_t)r * K + lu * 8);
        }
        __syncthreads();

#pragma unroll
        for (int kk = 0; kk < 4; kk++) {
            uint32_t af0[4], af1[4];
            ldm_x4(af0, sA_u + swz64(arow,      kk * 2 + au));
            ldm_x4(af1, sA_u + swz64(arow + 16, kk * 2 + au));
#pragma unroll
            for (int nb = 0; nb < 8; nb++) {
                uint32_t b0, b1;
                ldm_x2(b0, b1, sB_u + swz64(brow + nb * 8, kk * 2 + bu));
                mma16816(c[0][nb], af0, b0, b1);
                mma16816(c[1][nb], af1, b0, b1);
            }
        }
        __syncthreads();
    }

#pragma unroll
    for (int mi = 0; mi < 2; mi++) {
        int gr = m0 + wm * 32 + mi * 16 + (l >> 2);
#pragma unroll
        for (int nb = 0; nb < 8; nb++) {
            int gc = n0 + wn * 64 + nb * 8 + 2 * (l & 3);
            *(float2*)(C + (size_t)gr * N + gc)       = make_float2(c[mi][nb][0], c[mi][nb][1]);
            *(float2*)(C + (size_t)(gr + 8) * N + gc) = make_float2(c[mi][nb][2], c[mi][nb][3]);
        }
    }
}

__global__ void reduce4_kernel(const float* __restrict__ P, float* __restrict__ out, int n) {
    int i = blockIdx.x * blockDim.x + threadIdx.x;
    if (i * 4 >= n) return;
    float4 a = *(const float4*)(P + i * 4);
    float4 b = *(const float4*)(P + n + i * 4);
    float4 cc = *(const float4*)(P + 2 * n + i * 4);
    float4 d = *(const float4*)(P + 3 * n + i * 4);
    float4 r = make_float4(a.x + b.x + cc.x + d.x, a.y + b.y + cc.y + d.y,
                           a.z + b.z + cc.z + d.z, a.w + b.w + cc.w + d.w);
    *(float4*)(out + i * 4) = r;
}

// ---------------------------------------------------------------------------
// FA-2 attention, Br=128 q rows, Bc=64 keys, 8 warps, cp.async double buffer.
// SMEM: Q 32KB @0; buf b in {0,1}: K @32768+b*32768 (16KB), V @+16384.
// Q is pre-scaled by 1/sqrt(dh)*log2e, softmax via ex2.
// ---------------------------------------------------------------------------
#define ATTN_SMEM (32768 + 4 * 16384)   // 98304

__global__ __launch_bounds__(256, 1)
void attn_mma(const __half* __restrict__ Qh, const __half* __restrict__ Kh,
              const __half* __restrict__ Vh, __half* __restrict__ O) {
    extern __shared__ char smem[];
    const uint32_t sm_u = smem_u32(smem);
    const uint32_t sQ_u = sm_u;

    const int tid = threadIdx.x;
    const int w = tid >> 5, l = tid & 31;
    const int qt = blockIdx.x;        // 128-row query tile
    const int hq = blockIdx.y;
    const int g  = hq >> 2;
    const int nkb = 2 * qt + 2;       // number of 64-key tiles

    const __half* kg = Kh + (size_t)g * DH_N;
    const __half* vg = Vh + (size_t)g * DH_N;

    // prefetch Q (2048 units) + tile 0 K/V (2048 units) as group 0
    {
        const __half* qgp = Qh + (size_t)(qt * 128) * QDIM + hq * DH_N;
#pragma unroll
        for (int i = 0; i < 8; i++) {
            int idx = i * 256 + tid;
            int r = idx >> 4, u = idx & 15;
            cp16(sQ_u + swz(r, u), qgp + (size_t)r * QDIM + u * 8);
        }
#pragma unroll
        for (int i = 0; i < 4; i++) {
            int idx = i * 256 + tid;
            int r = idx >> 4, u = idx & 15;
            cp16(sm_u + 32768 + swz(r, u), kg + (size_t)r * KDIM + u * 8);
            cp16(sm_u + 49152 + swz(r, u), vg + (size_t)r * KDIM + u * 8);
        }
        CP_COMMIT();
    }

    uint32_t qf[8][4];
    float o[16][4];
#pragma unroll
    for (int i = 0; i < 16; i++)
#pragma unroll
        for (int j = 0; j < 4; j++) o[i][j] = 0.f;
    float m0 = -FLT_MAX, m1 = -FLT_MAX, l0 = 0.f, l1 = 0.f;

    const int qrow = w * 16 + (l & 7) + ((l >> 3) & 1) * 8;
    const int qu   = (l >> 4);
    const int krow = ((l >> 4) & 1) * 8 + (l & 7);     // x4: lanes 16-31 -> +8 rows
    const int ku   = (l >> 3) & 1;
    const int vrow = (l & 7) + ((l >> 3) & 1) * 8;
    const int vu   = (l >> 4) & 1;                     // x4t: lanes 16-31 -> next unit

    for (int kb = 0; kb < nkb; kb++) {
        const int has_next = (kb + 1 < nkb);
        if (has_next) {
            int tk = kb + 1;
            uint32_t kb_s = sm_u + 32768 + (tk & 1) * 32768;
#pragma unroll
            for (int i = 0; i < 4; i++) {
                int idx = i * 256 + tid;
                int r = idx >> 4, u = idx & 15;
                cp16(kb_s + swz(r, u),         kg + (size_t)(tk * 64 + r) * KDIM + u * 8);
                cp16(kb_s + 16384 + swz(r, u), vg + (size_t)(tk * 64 + r) * KDIM + u * 8);
            }
            CP_COMMIT();
            CP_WAIT(1);
        } else {
            CP_WAIT(0);
        }
        __syncthreads();

        const uint32_t sK_u = sm_u + 32768 + (kb & 1) * 32768;
        const uint32_t sV_u = sK_u + 16384;

        if (kb == 0) {
            // Q fragments now resident
#pragma unroll
            for (int kk = 0; kk < 8; kk++)
                ldm_x4(qf[kk], sQ_u + swz(qrow, kk * 2 + qu));
        }

        // ---- S = Q K^T ----
        float c[8][4];
#pragma unroll
        for (int nb = 0; nb < 8; nb++)
#pragma unroll
            for (int j = 0; j < 4; j++) c[nb][j] = 0.f;

#pragma unroll
        for (int kk = 0; kk < 8; kk++) {
#pragma unroll
            for (int np = 0; np < 4; np++) {
                uint32_t bf[4];
                ldm_x4(bf, sK_u + swz(np * 16 + krow, kk * 2 + ku));
                mma16816(c[2 * np],     qf[kk], bf[0], bf[1]);
                mma16816(c[2 * np + 1], qf[kk], bf[2], bf[3]);
            }
        }

        // ---- causal mask (only the last two key tiles can touch the diagonal) ----
        if (kb >= 2 * qt) {
            int r0 = qt * 128 + w * 16 + (l >> 2), r1 = r0 + 8;
            int cbase = kb * 64 + 2 * (l & 3);
#pragma unroll
            for (int nb = 0; nb < 8; nb++) {
                int cb = cbase + nb * 8;
                if (cb     > r0) c[nb][0] = -FLT_MAX;
                if (cb + 1 > r0) c[nb][1] = -FLT_MAX;
                if (cb     > r1) c[nb][2] = -FLT_MAX;
                if (cb + 1 > r1) c[nb][3] = -FLT_MAX;
            }
        }

        // ---- online softmax (scores pre-scaled; ex2) ----
        float mx0 = -FLT_MAX, mx1 = -FLT_MAX;
#pragma unroll
        for (int nb = 0; nb < 8; nb++) {
            mx0 = fmaxf(mx0, fmaxf(c[nb][0], c[nb][1]));
            mx1 = fmaxf(mx1, fmaxf(c[nb][2], c[nb][3]));
        }
        mx0 = fmaxf(mx0, __shfl_xor_sync(0xffffffffu, mx0, 1));
        mx0 = fmaxf(mx0, __shfl_xor_sync(0xffffffffu, mx0, 2));
        mx1 = fmaxf(mx1, __shfl_xor_sync(0xffffffffu, mx1, 1));
        mx1 = fmaxf(mx1, __shfl_xor_sync(0xffffffffu, mx1, 2));

        float mn0 = fmaxf(m0, mx0), mn1 = fmaxf(m1, mx1);
        float a0 = fast_ex2(m0 - mn0);
        float a1 = fast_ex2(m1 - mn1);
        m0 = mn0; m1 = mn1;
        l0 *= a0; l1 *= a1;

        float s0 = 0.f, s1 = 0.f;
#pragma unroll
        for (int nb = 0; nb < 8; nb++) {
            float p;
            p = fast_ex2(c[nb][0] - m0); c[nb][0] = p; s0 += p;
            p = fast_ex2(c[nb][1] - m0); c[nb][1] = p; s0 += p;
            p = fast_ex2(c[nb][2] - m1); c[nb][2] = p; s1 += p;
            p = fast_ex2(c[nb][3] - m1); c[nb][3] = p; s1 += p;
        }
        s0 += __shfl_xor_sync(0xffffffffu, s0, 1);
        s0 += __shfl_xor_sync(0xffffffffu, s0, 2);
        s1 += __shfl_xor_sync(0xffffffffu, s1, 1);
        s1 += __shfl_xor_sync(0xffffffffu, s1, 2);
        l0 += s0; l1 += s1;

#pragma unroll
        for (int i = 0; i < 16; i++) {
            o[i][0] *= a0; o[i][1] *= a0;
            o[i][2] *= a1; o[i][3] *= a1;
        }

        // ---- pack P ----
        uint32_t pf[4][4];
#pragma unroll
        for (int k2 = 0; k2 < 4; k2++) {
            pf[k2][0] = packh2(c[2 * k2][0],     c[2 * k2][1]);
            pf[k2][1] = packh2(c[2 * k2][2],     c[2 * k2][3]);
            pf[k2][2] = packh2(c[2 * k2 + 1][0], c[2 * k2 + 1][1]);
            pf[k2][3] = packh2(c[2 * k2 + 1][2], c[2 * k2 + 1][3]);
        }

        // ---- O += P V ----
#pragma unroll
        for (int k2 = 0; k2 < 4; k2++) {
            int row = k2 * 16 + vrow;
#pragma unroll
            for (int np = 0; np < 8; np++) {
                uint32_t bf[4];
                ldm_x4t(bf, sV_u + swz(row, np * 2 + vu));
                mma16816(o[2 * np],     pf[k2], bf[0], bf[1]);
                mma16816(o[2 * np + 1], pf[k2], bf[2], bf[3]);
            }
        }
        __syncthreads();
    }

    // ---- epilogue: fp16 O ----
    {
        float inv0 = 1.f / l0, inv1 = 1.f / l1;
        int gr0 = qt * 128 + w * 16 + (l >> 2), gr1 = gr0 + 8;
        __half* ob0 = O + (size_t)gr0 * QDIM + hq * DH_N + 2 * (l & 3);
        __half* ob1 = O + (size_t)gr1 * QDIM + hq * DH_N + 2 * (l & 3);
#pragma unroll
        for (int nb2 = 0; nb2 < 16; nb2++) {
            *(uint32_t*)(ob0 + nb2 * 8) = packh2(o[nb2][0] * inv0, o[nb2][1] * inv0);
            *(uint32_t*)(ob1 + nb2 * 8) = packh2(o[nb2][2] * inv1, o[nb2][3] * inv1);
        }
    }
}

// ---------------------------------------------------------------------------
// Launch
// ---------------------------------------------------------------------------
extern "C" void kernel_launch(void* const* d_in, const int* in_sizes, int n_in,
                              void* d_out, int out_size) {
    const float* q  = (const float*)d_in[0];
    const float* k  = (const float*)d_in[1];
    const float* v  = (const float*)d_in[2];
    // d_in[3] = mask (causal, reconstructed analytically)
    const float* Wq = (const float*)d_in[4];
    const float* Wk = (const float*)d_in[5];
    const float* Wv = (const float*)d_in[6];
    const float* Wo = (const float*)d_in[7];
    float* out = (float*)d_out;

    float *Qb, *Kb, *Vb, *Part;
    __half *Qh, *Kh, *Vh, *Oh, *xq, *xk, *xv, *Wqt, *Wkt, *Wvt, *Wot;
    cudaGetSymbolAddress((void**)&Qb, g_Q);
    cudaGetSymbolAddress((void**)&Kb, g_K);
    cudaGetSymbolAddress((void**)&Vb, g_V);
    cudaGetSymbolAddress((void**)&Qh, g_Qh);
    cudaGetSymbolAddress((void**)&Kh, g_Kh);
    cudaGetSymbolAddress((void**)&Vh, g_Vh);
    cudaGetSymbolAddress((void**)&Oh, g_Oh);
    cudaGetSymbolAddress((void**)&xq, g_xq);
    cudaGetSymbolAddress((void**)&xk, g_xk);
    cudaGetSymbolAddress((void**)&xv, g_xv);
    cudaGetSymbolAddress((void**)&Wqt, g_Wqt);
    cudaGetSymbolAddress((void**)&Wkt, g_Wkt);
    cudaGetSymbolAddress((void**)&Wvt, g_Wvt);
    cudaGetSymbolAddress((void**)&Wot, g_Wot);
    cudaGetSymbolAddress((void**)&Part, g_part);

    cudaFuncSetAttribute(attn_mma, cudaFuncAttributeMaxDynamicSharedMemorySize, ATTN_SMEM);

    invf_kernel<<<1, 128>>>();

    int nin = T_LEN * DIMM;
    f2h_kernel<<<(nin / 4 + 255) / 256, 256>>>(q, xq, nin);
    f2h_kernel<<<(nin / 4 + 255) / 256, 256>>>(k, xk, nin);
    f2h_kernel<<<(nin / 4 + 255) / 256, 256>>>(v, xv, nin);
    tcast_kernel<<<dim3(QDIM / 32, DIMM / 32), dim3(32, 32)>>>(Wq, Wqt, DIMM, QDIM);
    tcast_kernel<<<dim3(KDIM / 32, DIMM / 32), dim3(32, 32)>>>(Wk, Wkt, DIMM, KDIM);
    tcast_kernel<<<dim3(KDIM / 32, DIMM / 32), dim3(32, 32)>>>(Wv, Wvt, DIMM, KDIM);
    tcast_kernel<<<dim3(DIMM / 32, QDIM / 32), dim3(32, 32)>>>(Wo, Wot, QDIM, DIMM);

    hgemm<<<dim3(QDIM / 128, T_LEN / 128, 1), 256>>>(xq, Wqt, Qb, T_LEN, QDIM, DIMM, DIMM);
    hgemm<<<dim3(KDIM / 128, T_LEN / 128, 1), 256>>>(xk, Wkt, Kb, T_LEN, KDIM, DIMM, DIMM);
    hgemm<<<dim3(KDIM / 128, T_LEN / 128, 1), 256>>>(xv, Wvt, Vb, T_LEN, KDIM, DIMM, DIMM);

    // Q gets the softmax scale * log2e folded in
    rope_h<<<(T_LEN * HQ_N * 64 + 255) / 256, 256>>>(Qb, Qh, HQ_N, (float)Q_PREMUL);
    rope_h<<<(T_LEN * HK_N * 64 + 255) / 256, 256>>>(Kb, Kh, HK_N, 1.0f);
    rope_h<<<(T_LEN * HK_N * 64 + 255) / 256, 256>>>(Vb, Vh, HK_N, 1.0f);

    attn_mma<<<dim3(T_LEN / 128, HQ_N), 256, ATTN_SMEM>>>(Qh, Kh, Vh, Oh);

    hgemm<<<dim3(DIMM / 128, T_LEN / 128, 4), 256>>>(Oh, Wot, Part, T_LEN, DIMM, QDIM, QDIM / 4);
    reduce4_kernel<<<(T_LEN * DIMM / 4 + 255) / 256, 256>>>(Part, out, T_LEN * DIMM);
}

// round 6
// speedup vs baseline: 6.2177x; 1.1086x over previous
#include <cuda_runtime.h>
#include <cuda_fp16.h>
#include <math.h>
#include <float.h>
#include <stdint.h>

// ---------------------------------------------------------------------------
// Problem constants
// ---------------------------------------------------------------------------
#define T_LEN 2048
#define DIMM  256
#define HQ_N  32
#define HK_N  8
#define DH_N  128
#define QDIM  (HQ_N * DH_N)   // 4096
#define KDIM  (HK_N * DH_N)   // 1024

#define Q_PREMUL (0.08838834764831845 * 1.4426950408889634)

// Scratch (no cudaMalloc allowed)
__device__ __align__(16) float  g_Q[T_LEN * QDIM];
__device__ __align__(16) float  g_K[T_LEN * KDIM];
__device__ __align__(16) float  g_V[T_LEN * KDIM];
__device__ __align__(16) __half g_Qh[T_LEN * QDIM];
__device__ __align__(16) __half g_Kh[T_LEN * KDIM];
__device__ __align__(16) __half g_Vh[T_LEN * KDIM];
__device__ __align__(16) __half g_Oh[T_LEN * QDIM];
__device__ __align__(16) __half g_xq[T_LEN * DIMM];
__device__ __align__(16) __half g_xk[T_LEN * DIMM];
__device__ __align__(16) __half g_xv[T_LEN * DIMM];
__device__ __align__(16) __half g_Wqt[QDIM * DIMM];
__device__ __align__(16) __half g_Wkt[KDIM * DIMM];
__device__ __align__(16) __half g_Wvt[KDIM * DIMM];
__device__ __align__(16) __half g_Wot[DIMM * QDIM];
__device__ __align__(16) float  g_part[4 * T_LEN * DIMM];
__device__ double g_invf[DH_N];

// ---------------------------------------------------------------------------
// PTX helpers
// ---------------------------------------------------------------------------
__device__ __forceinline__ uint32_t smem_u32(const void* p) {
    uint32_t a;
    asm("{ .reg .u64 t; cvta.to.shared.u64 t, %1; cvt.u32.u64 %0, t; }" : "=r"(a) : "l"(p));
    return a;
}
__device__ __forceinline__ void ldm_x4(uint32_t* r, uint32_t addr) {
    asm volatile("ldmatrix.sync.aligned.m8n8.x4.shared.b16 {%0,%1,%2,%3}, [%4];"
                 : "=r"(r[0]), "=r"(r[1]), "=r"(r[2]), "=r"(r[3]) : "r"(addr));
}
__device__ __forceinline__ void ldm_x2(uint32_t& r0, uint32_t& r1, uint32_t addr) {
    asm volatile("ldmatrix.sync.aligned.m8n8.x2.shared.b16 {%0,%1}, [%2];"
                 : "=r"(r0), "=r"(r1) : "r"(addr));
}
__device__ __forceinline__ void ldm_x4t(uint32_t* r, uint32_t addr) {
    asm volatile("ldmatrix.sync.aligned.m8n8.x4.trans.shared.b16 {%0,%1,%2,%3}, [%4];"
                 : "=r"(r[0]), "=r"(r[1]), "=r"(r[2]), "=r"(r[3]) : "r"(addr));
}
__device__ __forceinline__ void mma16816(float* c, const uint32_t* a, uint32_t b0, uint32_t b1) {
    asm volatile(
        "mma.sync.aligned.m16n8k16.row.col.f32.f16.f16.f32 "
        "{%0,%1,%2,%3}, {%4,%5,%6,%7}, {%8,%9}, {%0,%1,%2,%3};"
        : "+f"(c[0]), "+f"(c[1]), "+f"(c[2]), "+f"(c[3])
        : "r"(a[0]), "r"(a[1]), "r"(a[2]), "r"(a[3]), "r"(b0), "r"(b1));
}
__device__ __forceinline__ uint32_t packh2(float lo, float hi) {
    __half2 h = __float22half2_rn(make_float2(lo, hi));
    return *(uint32_t*)&h;
}
__device__ __forceinline__ float fast_ex2(float x) {
    float y;
    asm("ex2.approx.ftz.f32 %0, %1;" : "=f"(y) : "f"(x));
    return y;
}
__device__ __forceinline__ void cp16(uint32_t saddr, const void* g) {
    asm volatile("cp.async.cg.shared.global [%0], [%1], 16;" :: "r"(saddr), "l"(g));
}
#define CP_COMMIT() asm volatile("cp.async.commit_group;" ::: "memory")
#define CP_WAIT(n)  asm volatile("cp.async.wait_group %0;" :: "n"(n) : "memory")

__device__ __forceinline__ uint32_t swz(int r, int u) {
    return (uint32_t)(r * 256 + (((u & 8) | ((u ^ r) & 7)) << 4));
}
__device__ __forceinline__ uint32_t swz64(int r, int u) {
    return (uint32_t)(r * 128 + (((u ^ r) & 7) << 4));
}

// ---------------------------------------------------------------------------
// Fused prep 1: casts (q,k,v -> fp16) + invf. grid (512,3), 256 thr.
// ---------------------------------------------------------------------------
__global__ void castall_kernel(const float* __restrict__ q, const float* __restrict__ k,
                               const float* __restrict__ v) {
    if (blockIdx.z == 0 && blockIdx.x == 0 && threadIdx.x < DH_N)
        g_invf[threadIdx.x] = pow(10000.0, -(double)threadIdx.x / 128.0);

    const float* X = (blockIdx.z == 0) ? q : (blockIdx.z == 1) ? k : v;
    __half* Y = (blockIdx.z == 0) ? g_xq : (blockIdx.z == 1) ? g_xk : g_xv;
    int i = blockIdx.x * blockDim.x + threadIdx.x;
    float4 val = *(const float4*)(X + i * 4);
    __half2 a = __float22half2_rn(make_float2(val.x, val.y));
    __half2 b = __float22half2_rn(make_float2(val.z, val.w));
    *(uint32_t*)(Y + i * 4)     = *(uint32_t*)&a;
    *(uint32_t*)(Y + i * 4 + 2) = *(uint32_t*)&b;
}

// ---------------------------------------------------------------------------
// Fused prep 2: all 4 weight transposes+casts. 256 thr (32x8), range-decoded.
// Tile counts: Wq 128x8=1024, Wk 32x8=256, Wv 256, Wo 8x128=1024. Total 2560.
// ---------------------------------------------------------------------------
__global__ void tcastall_kernel(const float* __restrict__ Wq, const float* __restrict__ Wk,
                                const float* __restrict__ Wv, const float* __restrict__ Wo) {
    __shared__ float t[32][33];
    int b = blockIdx.x;
    const float* W; __half* Wt; int K, N, ntile_n, tt;
    if (b < 1024)      { W = Wq; Wt = g_Wqt; K = DIMM; N = QDIM; ntile_n = 128; tt = b; }
    else if (b < 1280) { W = Wk; Wt = g_Wkt; K = DIMM; N = KDIM; ntile_n = 32;  tt = b - 1024; }
    else if (b < 1536) { W = Wv; Wt = g_Wvt; K = DIMM; N = KDIM; ntile_n = 32;  tt = b - 1280; }
    else               { W = Wo; Wt = g_Wot; K = QDIM; N = DIMM; ntile_n = 8;   tt = b - 1536; }
    int n0 = (tt % ntile_n) * 32, k0 = (tt / ntile_n) * 32;
    int tx = threadIdx.x & 31, ty = threadIdx.x >> 5;   // 32 x 8
#pragma unroll
    for (int i = 0; i < 4; i++)
        t[ty + i * 8][tx] = W[(size_t)(k0 + ty + i * 8) * N + n0 + tx];
    __syncthreads();
#pragma unroll
    for (int i = 0; i < 4; i++)
        Wt[(size_t)(n0 + ty + i * 8) * K + k0 + tx] = __float2half_rn(t[tx][ty + i * 8]);
}

// ---------------------------------------------------------------------------
// Fused RoPE for Q,K,V. Segment-decoded flat index. pos = 6144 + t.
// ---------------------------------------------------------------------------
#define NQ_ROPE (T_LEN * HQ_N * 64)
#define NK_ROPE (T_LEN * HK_N * 64)

__global__ void rope_all(float q_mult) {
    int idx = blockIdx.x * blockDim.x + threadIdx.x;
    const float* X; __half* Y; int nh; float mult;
    if (idx < NQ_ROPE) {
        X = g_Q; Y = g_Qh; nh = HQ_N; mult = q_mult;
    } else if (idx < NQ_ROPE + NK_ROPE) {
        X = g_K; Y = g_Kh; nh = HK_N; mult = 1.0f; idx -= NQ_ROPE;
    } else {
        X = g_V; Y = g_Vh; nh = HK_N; mult = 1.0f; idx -= NQ_ROPE + NK_ROPE;
    }
    int d = idx & 63;
    int h = (idx >> 6) % nh;
    int t = idx / (64 * nh);

    size_t base = (size_t)t * nh * DH_N + (size_t)h * DH_N;
    double pos = (double)(6144 + t);
    double f1 = pos * g_invf[d];
    double f2 = pos * g_invf[d + 64];
    const double inv2pi = 0.15915494309189535;
    const double twopi  = 6.283185307179586;
    f1 -= floor(f1 * inv2pi) * twopi;
    f2 -= floor(f2 * inv2pi) * twopi;
    float s1, c1, s2, c2;
    sincosf((float)f1, &s1, &c1);
    sincosf((float)f2, &s2, &c2);
    float x1 = X[base + d], x2 = X[base + d + 64];
    Y[base + d]      = __float2half_rn((x1 * c1 - x2 * s1) * mult);
    Y[base + d + 64] = __float2half_rn((x2 * c2 + x1 * s2) * mult);
}

// ---------------------------------------------------------------------------
// fp16 tensor-core GEMM body: C[M,N] = A[M,K] * Bt[N,K]^T, fp32 accum/out.
// ---------------------------------------------------------------------------
__device__ __forceinline__
void hgemm_body(const __half* __restrict__ A, const __half* __restrict__ Bt,
                float* __restrict__ C, int M, int N, int K, int klen, int kstart) {
    __shared__ __align__(16) __half sA[128 * 64];
    __shared__ __align__(16) __half sB[128 * 64];
    const uint32_t sA_u = smem_u32(sA);
    const uint32_t sB_u = smem_u32(sB);

    const int tid = threadIdx.x;
    const int w = tid >> 5, l = tid & 31;
    const int wm = w >> 1, wn = w & 1;
    const int m0 = blockIdx.y * 128, n0 = blockIdx.x * 128;

    float c[2][8][4];
#pragma unroll
    for (int mi = 0; mi < 2; mi++)
#pragma unroll
        for (int nb = 0; nb < 8; nb++)
#pragma unroll
            for (int j = 0; j < 4; j++) c[mi][nb][j] = 0.f;

    const int lr = tid >> 3, lu = tid & 7;
    const int arow = wm * 32 + (l & 7) + ((l >> 3) & 1) * 8;
    const int au = (l >> 4);
    const int brow = wn * 64 + (l & 7);
    const int bu = (l >> 3) & 1;

    for (int kc = 0; kc < klen; kc += 64) {
        const __half* Ab = A + (size_t)m0 * K + kstart + kc;
        const __half* Bb = Bt + (size_t)n0 * K + kstart + kc;
#pragma unroll
        for (int i = 0; i < 4; i++) {
            int r = i * 32 + lr;
            *(uint4*)((char*)sA + swz64(r, lu)) = *(const uint4*)(Ab + (size_t)r * K + lu * 8);
            *(uint4*)((char*)sB + swz64(r, lu)) = *(const uint4*)(Bb + (size_t)r * K + lu * 8);
        }
        __syncthreads();

#pragma unroll
        for (int kk = 0; kk < 4; kk++) {
            uint32_t af0[4], af1[4];
            ldm_x4(af0, sA_u + swz64(arow,      kk * 2 + au));
            ldm_x4(af1, sA_u + swz64(arow + 16, kk * 2 + au));
#pragma unroll
            for (int nb = 0; nb < 8; nb++) {
                uint32_t b0, b1;
                ldm_x2(b0, b1, sB_u + swz64(brow + nb * 8, kk * 2 + bu));
                mma16816(c[0][nb], af0, b0, b1);
                mma16816(c[1][nb], af1, b0, b1);
            }
        }
        __syncthreads();
    }

#pragma unroll
    for (int mi = 0; mi < 2; mi++) {
        int gr = m0 + wm * 32 + mi * 16 + (l >> 2);
#pragma unroll
        for (int nb = 0; nb < 8; nb++) {
            int gc = n0 + wn * 64 + nb * 8 + 2 * (l & 3);
            *(float2*)(C + (size_t)gr * N + gc)       = make_float2(c[mi][nb][0], c[mi][nb][1]);
            *(float2*)(C + (size_t)(gr + 8) * N + gc) = make_float2(c[mi][nb][2], c[mi][nb][3]);
        }
    }
}

// Q projection: grid (QDIM/128, T_LEN/128)
__global__ __launch_bounds__(256, 2)
void hgemm_q(const __half* __restrict__ A, const __half* __restrict__ Bt,
             float* __restrict__ C) {
    hgemm_body(A, Bt, C, T_LEN, QDIM, DIMM, DIMM, 0);
}
// K+V projections batched on z: grid (KDIM/128, T_LEN/128, 2)
__global__ __launch_bounds__(256, 2)
void hgemm_kv() {
    if (blockIdx.z == 0) hgemm_body(g_xk, g_Wkt, g_K, T_LEN, KDIM, DIMM, DIMM, 0);
    else                 hgemm_body(g_xv, g_Wvt, g_V, T_LEN, KDIM, DIMM, DIMM, 0);
}
// O projection split-K=4: grid (DIMM/128, T_LEN/128, 4)
__global__ __launch_bounds__(256, 2)
void hgemm_o(float* __restrict__ Part) {
    hgemm_body(g_Oh, g_Wot, Part + (size_t)blockIdx.z * T_LEN * DIMM,
               T_LEN, DIMM, QDIM, QDIM / 4, blockIdx.z * (QDIM / 4));
}

__global__ void reduce4_kernel(const float* __restrict__ P, float* __restrict__ out, int n) {
    int i = blockIdx.x * blockDim.x + threadIdx.x;
    if (i * 4 >= n) return;
    float4 a = *(const float4*)(P + i * 4);
    float4 b = *(const float4*)(P + n + i * 4);
    float4 cc = *(const float4*)(P + 2 * n + i * 4);
    float4 d = *(const float4*)(P + 3 * n + i * 4);
    float4 r = make_float4(a.x + b.x + cc.x + d.x, a.y + b.y + cc.y + d.y,
                           a.z + b.z + cc.z + d.z, a.w + b.w + cc.w + d.w);
    *(float4*)(out + i * 4) = r;
}

// ---------------------------------------------------------------------------
// FA-2 attention, Br=128, Bc=64, 8 warps, cp.async double buffer.
// Longest-first: qt = gridDim.x-1-blockIdx.x so 32-iter blocks launch first.
// ---------------------------------------------------------------------------
#define ATTN_SMEM (32768 + 4 * 16384)   // 98304

__global__ __launch_bounds__(256, 1)
void attn_mma(const __half* __restrict__ Qh, const __half* __restrict__ Kh,
              const __half* __restrict__ Vh, __half* __restrict__ O) {
    extern __shared__ char smem[];
    const uint32_t sm_u = smem_u32(smem);
    const uint32_t sQ_u = sm_u;

    const int tid = threadIdx.x;
    const int w = tid >> 5, l = tid & 31;
    const int qt = gridDim.x - 1 - blockIdx.x;   // longest blocks first
    const int hq = blockIdx.y;
    const int g  = hq >> 2;
    const int nkb = 2 * qt + 2;

    const __half* kg = Kh + (size_t)g * DH_N;
    const __half* vg = Vh + (size_t)g * DH_N;

    {
        const __half* qgp = Qh + (size_t)(qt * 128) * QDIM + hq * DH_N;
#pragma unroll
        for (int i = 0; i < 8; i++) {
            int idx = i * 256 + tid;
            int r = idx >> 4, u = idx & 15;
            cp16(sQ_u + swz(r, u), qgp + (size_t)r * QDIM + u * 8);
        }
#pragma unroll
        for (int i = 0; i < 4; i++) {
            int idx = i * 256 + tid;
            int r = idx >> 4, u = idx & 15;
            cp16(sm_u + 32768 + swz(r, u), kg + (size_t)r * KDIM + u * 8);
            cp16(sm_u + 49152 + swz(r, u), vg + (size_t)r * KDIM + u * 8);
        }
        CP_COMMIT();
    }

    uint32_t qf[8][4];
    float o[16][4];
#pragma unroll
    for (int i = 0; i < 16; i++)
#pragma unroll
        for (int j = 0; j < 4; j++) o[i][j] = 0.f;
    float m0 = -FLT_MAX, m1 = -FLT_MAX, l0 = 0.f, l1 = 0.f;

    const int qrow = w * 16 + (l & 7) + ((l >> 3) & 1) * 8;
    const int qu   = (l >> 4);
    const int krow = ((l >> 4) & 1) * 8 + (l & 7);
    const int ku   = (l >> 3) & 1;
    const int vrow = (l & 7) + ((l >> 3) & 1) * 8;
    const int vu   = (l >> 4) & 1;

    for (int kb = 0; kb < nkb; kb++) {
        const int has_next = (kb + 1 < nkb);
        if (has_next) {
            int tk = kb + 1;
            uint32_t kb_s = sm_u + 32768 + (tk & 1) * 32768;
#pragma unroll
            for (int i = 0; i < 4; i++) {
                int idx = i * 256 + tid;
                int r = idx >> 4, u = idx & 15;
                cp16(kb_s + swz(r, u),         kg + (size_t)(tk * 64 + r) * KDIM + u * 8);
                cp16(kb_s + 16384 + swz(r, u), vg + (size_t)(tk * 64 + r) * KDIM + u * 8);
            }
            CP_COMMIT();
            CP_WAIT(1);
        } else {
            CP_WAIT(0);
        }
        __syncthreads();

        const uint32_t sK_u = sm_u + 32768 + (kb & 1) * 32768;
        const uint32_t sV_u = sK_u + 16384;

        if (kb == 0) {
#pragma unroll
            for (int kk = 0; kk < 8; kk++)
                ldm_x4(qf[kk], sQ_u + swz(qrow, kk * 2 + qu));
        }

        float c[8][4];
#pragma unroll
        for (int nb = 0; nb < 8; nb++)
#pragma unroll
            for (int j = 0; j < 4; j++) c[nb][j] = 0.f;

#pragma unroll
        for (int kk = 0; kk < 8; kk++) {
#pragma unroll
            for (int np = 0; np < 4; np++) {
                uint32_t bf[4];
                ldm_x4(bf, sK_u + swz(np * 16 + krow, kk * 2 + ku));
                mma16816(c[2 * np],     qf[kk], bf[0], bf[1]);
                mma16816(c[2 * np + 1], qf[kk], bf[2], bf[3]);
            }
        }

        if (kb >= 2 * qt) {
            int r0 = qt * 128 + w * 16 + (l >> 2), r1 = r0 + 8;
            int cbase = kb * 64 + 2 * (l & 3);
#pragma unroll
            for (int nb = 0; nb < 8; nb++) {
                int cb = cbase + nb * 8;
                if (cb     > r0) c[nb][0] = -FLT_MAX;
                if (cb + 1 > r0) c[nb][1] = -FLT_MAX;
                if (cb     > r1) c[nb][2] = -FLT_MAX;
                if (cb + 1 > r1) c[nb][3] = -FLT_MAX;
            }
        }

        float mx0 = -FLT_MAX, mx1 = -FLT_MAX;
#pragma unroll
        for (int nb = 0; nb < 8; nb++) {
            mx0 = fmaxf(mx0, fmaxf(c[nb][0], c[nb][1]));
            mx1 = fmaxf(mx1, fmaxf(c[nb][2], c[nb][3]));
        }
        mx0 = fmaxf(mx0, __shfl_xor_sync(0xffffffffu, mx0, 1));
        mx0 = fmaxf(mx0, __shfl_xor_sync(0xffffffffu, mx0, 2));
        mx1 = fmaxf(mx1, __shfl_xor_sync(0xffffffffu, mx1, 1));
        mx1 = fmaxf(mx1, __shfl_xor_sync(0xffffffffu, mx1, 2));

        float mn0 = fmaxf(m0, mx0), mn1 = fmaxf(m1, mx1);
        float a0 = fast_ex2(m0 - mn0);
        float a1 = fast_ex2(m1 - mn1);
        m0 = mn0; m1 = mn1;
        l0 *= a0; l1 *= a1;

        float s0 = 0.f, s1 = 0.f;
#pragma unroll
        for (int nb = 0; nb < 8; nb++) {
            float p;
            p = fast_ex2(c[nb][0] - m0); c[nb][0] = p; s0 += p;
            p = fast_ex2(c[nb][1] - m0); c[nb][1] = p; s0 += p;
            p = fast_ex2(c[nb][2] - m1); c[nb][2] = p; s1 += p;
            p = fast_ex2(c[nb][3] - m1); c[nb][3] = p; s1 += p;
        }
        s0 += __shfl_xor_sync(0xffffffffu, s0, 1);
        s0 += __shfl_xor_sync(0xffffffffu, s0, 2);
        s1 += __shfl_xor_sync(0xffffffffu, s1, 1);
        s1 += __shfl_xor_sync(0xffffffffu, s1, 2);
        l0 += s0; l1 += s1;

#pragma unroll
        for (int i = 0; i < 16; i++) {
            o[i][0] *= a0; o[i][1] *= a0;
            o[i][2] *= a1; o[i][3] *= a1;
        }

        uint32_t pf[4][4];
#pragma unroll
        for (int k2 = 0; k2 < 4; k2++) {
            pf[k2][0] = packh2(c[2 * k2][0],     c[2 * k2][1]);
            pf[k2][1] = packh2(c[2 * k2][2],     c[2 * k2][3]);
            pf[k2][2] = packh2(c[2 * k2 + 1][0], c[2 * k2 + 1][1]);
            pf[k2][3] = packh2(c[2 * k2 + 1][2], c[2 * k2 + 1][3]);
        }

#pragma unroll
        for (int k2 = 0; k2 < 4; k2++) {
            int row = k2 * 16 + vrow;
#pragma unroll
            for (int np = 0; np < 8; np++) {
                uint32_t bf[4];
                ldm_x4t(bf, sV_u + swz(row, np * 2 + vu));
                mma16816(o[2 * np],     pf[k2], bf[0], bf[1]);
                mma16816(o[2 * np + 1], pf[k2], bf[2], bf[3]);
            }
        }
        __syncthreads();
    }

    {
        float inv0 = 1.f / l0, inv1 = 1.f / l1;
        int gr0 = qt * 128 + w * 16 + (l >> 2), gr1 = gr0 + 8;
        __half* ob0 = O + (size_t)gr0 * QDIM + hq * DH_N + 2 * (l & 3);
        __half* ob1 = O + (size_t)gr1 * QDIM + hq * DH_N + 2 * (l & 3);
#pragma unroll
        for (int nb2 = 0; nb2 < 16; nb2++) {
            *(uint32_t*)(ob0 + nb2 * 8) = packh2(o[nb2][0] * inv0, o[nb2][1] * inv0);
            *(uint32_t*)(ob1 + nb2 * 8) = packh2(o[nb2][2] * inv1, o[nb2][3] * inv1);
        }
    }
}

// ---------------------------------------------------------------------------
// Launch
// ---------------------------------------------------------------------------
extern "C" void kernel_launch(void* const* d_in, const int* in_sizes, int n_in,
                              void* d_out, int out_size) {
    const float* q  = (const float*)d_in[0];
    const float* k  = (const float*)d_in[1];
    const float* v  = (const float*)d_in[2];
    // d_in[3] = mask (causal, reconstructed analytically)
    const float* Wq = (const float*)d_in[4];
    const float* Wk = (const float*)d_in[5];
    const float* Wv = (const float*)d_in[6];
    const float* Wo = (const float*)d_in[7];
    float* out = (float*)d_out;

    float *Part;
    __half *Qh, *Kh, *Vh, *Oh, *xq, *Wqt;
    float *Qb;
    cudaGetSymbolAddress((void**)&Qb, g_Q);
    cudaGetSymbolAddress((void**)&Qh, g_Qh);
    cudaGetSymbolAddress((void**)&Kh, g_Kh);
    cudaGetSymbolAddress((void**)&Vh, g_Vh);
    cudaGetSymbolAddress((void**)&Oh, g_Oh);
    cudaGetSymbolAddress((void**)&xq, g_xq);
    cudaGetSymbolAddress((void**)&Wqt, g_Wqt);
    cudaGetSymbolAddress((void**)&Part, g_part);

    cudaFuncSetAttribute(attn_mma, cudaFuncAttributeMaxDynamicSharedMemorySize, ATTN_SMEM);

    // prep: casts + invf (1 launch), weight transposes (1 launch)
    castall_kernel<<<dim3(512, 1, 3), 256>>>(q, k, v);
    tcastall_kernel<<<2560, 256>>>(Wq, Wk, Wv, Wo);

    // projections
    hgemm_q<<<dim3(QDIM / 128, T_LEN / 128), 256>>>(xq, Wqt, Qb);
    hgemm_kv<<<dim3(KDIM / 128, T_LEN / 128, 2), 256>>>();

    // fused RoPE (Q scaled by softmax scale * log2e)
    rope_all<<<(NQ_ROPE + 2 * NK_ROPE) / 256, 256>>>((float)Q_PREMUL);

    // attention
    attn_mma<<<dim3(T_LEN / 128, HQ_N), 256, ATTN_SMEM>>>(Qh, Kh, Vh, Oh);

    // output projection split-K=4 + reduce
    hgemm_o<<<dim3(DIMM / 128, T_LEN / 128, 4), 256>>>(Part);
    reduce4_kernel<<<(T_LEN * DIMM / 4 + 255) / 256, 256>>>(Part, out, T_LEN * DIMM);
}

// round 7
// speedup vs baseline: 8.0971x; 1.3023x over previous
#include <cuda_runtime.h>
#include <cuda_fp16.h>
#include <math.h>
#include <float.h>
#include <stdint.h>

// ---------------------------------------------------------------------------
// Problem constants
// ---------------------------------------------------------------------------
#define T_LEN 2048
#define DIMM  256
#define HQ_N  32
#define HK_N  8
#define DH_N  128
#define QDIM  (HQ_N * DH_N)   // 4096
#define KDIM  (HK_N * DH_N)   // 1024

#define Q_PREMUL (0.08838834764831845 * 1.4426950408889634)

// Scratch (no cudaMalloc allowed)
__device__ __align__(16) __half g_Qh[T_LEN * QDIM];
__device__ __align__(16) __half g_Kh[T_LEN * KDIM];
__device__ __align__(16) __half g_Vh[T_LEN * KDIM];
__device__ __align__(16) __half g_Oh[T_LEN * QDIM];
__device__ __align__(16) __half g_xq[T_LEN * DIMM];
__device__ __align__(16) __half g_xk[T_LEN * DIMM];
__device__ __align__(16) __half g_xv[T_LEN * DIMM];
__device__ __align__(16) __half g_Wqt[QDIM * DIMM];
__device__ __align__(16) __half g_Wkt[KDIM * DIMM];
__device__ __align__(16) __half g_Wvt[KDIM * DIMM];
__device__ __align__(16) __half g_Wot[DIMM * QDIM];
__device__ __align__(16) float  g_part[8 * T_LEN * DIMM];
__device__ __align__(16) float4 g_rope[T_LEN * 64];   // (cos1,sin1,cos2,sin2) per (t, d<64)

// ---------------------------------------------------------------------------
// PTX helpers
// ---------------------------------------------------------------------------
__device__ __forceinline__ uint32_t smem_u32(const void* p) {
    uint32_t a;
    asm("{ .reg .u64 t; cvta.to.shared.u64 t, %1; cvt.u32.u64 %0, t; }" : "=r"(a) : "l"(p));
    return a;
}
__device__ __forceinline__ void ldm_x4(uint32_t* r, uint32_t addr) {
    asm volatile("ldmatrix.sync.aligned.m8n8.x4.shared.b16 {%0,%1,%2,%3}, [%4];"
                 : "=r"(r[0]), "=r"(r[1]), "=r"(r[2]), "=r"(r[3]) : "r"(addr));
}
__device__ __forceinline__ void ldm_x2(uint32_t& r0, uint32_t& r1, uint32_t addr) {
    asm volatile("ldmatrix.sync.aligned.m8n8.x2.shared.b16 {%0,%1}, [%2];"
                 : "=r"(r0), "=r"(r1) : "r"(addr));
}
__device__ __forceinline__ void ldm_x4t(uint32_t* r, uint32_t addr) {
    asm volatile("ldmatrix.sync.aligned.m8n8.x4.trans.shared.b16 {%0,%1,%2,%3}, [%4];"
                 : "=r"(r[0]), "=r"(r[1]), "=r"(r[2]), "=r"(r[3]) : "r"(addr));
}
__device__ __forceinline__ void mma16816(float* c, const uint32_t* a, uint32_t b0, uint32_t b1) {
    asm volatile(
        "mma.sync.aligned.m16n8k16.row.col.f32.f16.f16.f32 "
        "{%0,%1,%2,%3}, {%4,%5,%6,%7}, {%8,%9}, {%0,%1,%2,%3};"
        : "+f"(c[0]), "+f"(c[1]), "+f"(c[2]), "+f"(c[3])
        : "r"(a[0]), "r"(a[1]), "r"(a[2]), "r"(a[3]), "r"(b0), "r"(b1));
}
__device__ __forceinline__ uint32_t packh2(float lo, float hi) {
    __half2 h = __float22half2_rn(make_float2(lo, hi));
    return *(uint32_t*)&h;
}
__device__ __forceinline__ float fast_ex2(float x) {
    float y;
    asm("ex2.approx.ftz.f32 %0, %1;" : "=f"(y) : "f"(x));
    return y;
}
__device__ __forceinline__ void cp16(uint32_t saddr, const void* g) {
    asm volatile("cp.async.cg.shared.global [%0], [%1], 16;" :: "r"(saddr), "l"(g));
}
#define CP_COMMIT() asm volatile("cp.async.commit_group;" ::: "memory")
#define CP_WAIT(n)  asm volatile("cp.async.wait_group %0;" :: "n"(n) : "memory")

__device__ __forceinline__ uint32_t swz(int r, int u) {
    return (uint32_t)(r * 256 + (((u & 8) | ((u ^ r) & 7)) << 4));
}
__device__ __forceinline__ uint32_t swz64(int r, int u) {
    return (uint32_t)(r * 128 + (((u ^ r) & 7) << 4));
}

// ---------------------------------------------------------------------------
// Prep 1: input casts + rope cos/sin table. grid (512,1,3), 256 thr.
// ---------------------------------------------------------------------------
__global__ void castall_kernel(const float* __restrict__ q, const float* __restrict__ k,
                               const float* __restrict__ v) {
    int i = blockIdx.x * blockDim.x + threadIdx.x;
    if (blockIdx.z == 0) {
        // rope table: i in [0, 2048*64)
        int t = i >> 6, d = i & 63;
        double pos = 6144.0 + (double)t;
        double if1 = pow(10000.0, -(double)d / 128.0);
        double if2 = pow(10000.0, -(double)(d + 64) / 128.0);
        double f1 = pos * if1, f2 = pos * if2;
        const double inv2pi = 0.15915494309189535;
        const double twopi  = 6.283185307179586;
        f1 -= floor(f1 * inv2pi) * twopi;
        f2 -= floor(f2 * inv2pi) * twopi;
        float s1, c1, s2, c2;
        sincosf((float)f1, &s1, &c1);
        sincosf((float)f2, &s2, &c2);
        g_rope[i] = make_float4(c1, s1, c2, s2);
    }
    const float* X = (blockIdx.z == 0) ? q : (blockIdx.z == 1) ? k : v;
    __half* Y = (blockIdx.z == 0) ? g_xq : (blockIdx.z == 1) ? g_xk : g_xv;
    float4 val = *(const float4*)(X + i * 4);
    __half2 a = __float22half2_rn(make_float2(val.x, val.y));
    __half2 b = __float22half2_rn(make_float2(val.z, val.w));
    *(uint32_t*)(Y + i * 4)     = *(uint32_t*)&a;
    *(uint32_t*)(Y + i * 4 + 2) = *(uint32_t*)&b;
}

// ---------------------------------------------------------------------------
// Prep 2: all 4 weight transposes+casts. 256 thr (32x8), range-decoded.
// ---------------------------------------------------------------------------
__global__ void tcastall_kernel(const float* __restrict__ Wq, const float* __restrict__ Wk,
                                const float* __restrict__ Wv, const float* __restrict__ Wo) {
    __shared__ float t[32][33];
    int b = blockIdx.x;
    const float* W; __half* Wt; int K, N, ntile_n, tt;
    if (b < 1024)      { W = Wq; Wt = g_Wqt; K = DIMM; N = QDIM; ntile_n = 128; tt = b; }
    else if (b < 1280) { W = Wk; Wt = g_Wkt; K = DIMM; N = KDIM; ntile_n = 32;  tt = b - 1024; }
    else if (b < 1536) { W = Wv; Wt = g_Wvt; K = DIMM; N = KDIM; ntile_n = 32;  tt = b - 1280; }
    else               { W = Wo; Wt = g_Wot; K = QDIM; N = DIMM; ntile_n = 8;   tt = b - 1536; }
    int n0 = (tt % ntile_n) * 32, k0 = (tt / ntile_n) * 32;
    int tx = threadIdx.x & 31, ty = threadIdx.x >> 5;
#pragma unroll
    for (int i = 0; i < 4; i++)
        t[ty + i * 8][tx] = W[(size_t)(k0 + ty + i * 8) * N + n0 + tx];
    __syncthreads();
#pragma unroll
    for (int i = 0; i < 4; i++)
        Wt[(size_t)(n0 + ty + i * 8) * K + k0 + tx] = __float2half_rn(t[tx][ty + i * 8]);
}

// ---------------------------------------------------------------------------
// Pipelined fp16 GEMM body. C = A[M,K] * Bt[N,K]^T.
// Warp n-columns remapped: warp wn owns cols [wn*32, wn*32+32) U [wn*32+64, +96)
// so rope pairs (d, d+64) are thread-local (c[nb] / c[nb+4], nb<4).
// ROPE=1: apply rope (table) * mult, write fp16 to Y. ROPE=0: write fp32 to C.
// Dynamic smem: 2 buffers x (A 16KB + B 16KB) = 64KB.
// ---------------------------------------------------------------------------
#define GEMM_SMEM 65536

__device__ __forceinline__
void gemm_load(uint32_t sbuf, const __half* Ab, const __half* Bb, int K, int tid) {
    int lr = tid >> 3, lu = tid & 7;
#pragma unroll
    for (int i = 0; i < 4; i++) {
        int r = i * 32 + lr;
        cp16(sbuf + swz64(r, lu),         Ab + (size_t)r * K + lu * 8);
        cp16(sbuf + 16384 + swz64(r, lu), Bb + (size_t)r * K + lu * 8);
    }
}

template <int ROPE>
__device__ __forceinline__
void hgemm_body(const __half* __restrict__ A, const __half* __restrict__ Bt,
                float* __restrict__ C, __half* __restrict__ Y,
                int M, int N, int K, int klen, int kstart,
                int m_t, int n_t, float mult) {
    extern __shared__ char ds[];
    const uint32_t s_u = smem_u32(ds);

    const int tid = threadIdx.x;
    const int w = tid >> 5, l = tid & 31;
    const int wm = w >> 1, wn = w & 1;
    const int m0 = m_t * 128, n0 = n_t * 128;
    const int nk = klen >> 6;

    const __half* Ab = A + (size_t)m0 * K + kstart;
    const __half* Bb = Bt + (size_t)n0 * K + kstart;

    gemm_load(s_u, Ab, Bb, K, tid);
    CP_COMMIT();

    float c[2][8][4];
#pragma unroll
    for (int mi = 0; mi < 2; mi++)
#pragma unroll
        for (int nb = 0; nb < 8; nb++)
#pragma unroll
            for (int j = 0; j < 4; j++) c[mi][nb][j] = 0.f;

    const int arow = wm * 32 + (l & 7) + ((l >> 3) & 1) * 8;
    const int au = l >> 4;
    const int brow = wn * 32 + (l & 7);
    const int bu = (l >> 3) & 1;

    for (int i = 0; i < nk; i++) {
        if (i + 1 < nk) {
            gemm_load(s_u + ((i + 1) & 1) * 32768, Ab + (i + 1) * 64, Bb + (i + 1) * 64, K, tid);
            CP_COMMIT();
            CP_WAIT(1);
        } else {
            CP_WAIT(0);
        }
        __syncthreads();

        uint32_t sA_u = s_u + (i & 1) * 32768;
        uint32_t sB_u = sA_u + 16384;
#pragma unroll
        for (int kk = 0; kk < 4; kk++) {
            uint32_t af0[4], af1[4];
            ldm_x4(af0, sA_u + swz64(arow,      kk * 2 + au));
            ldm_x4(af1, sA_u + swz64(arow + 16, kk * 2 + au));
#pragma unroll
            for (int nb = 0; nb < 8; nb++) {
                int r = brow + (nb & 3) * 8 + (nb >> 2) * 64;
                uint32_t b0, b1;
                ldm_x2(b0, b1, sB_u + swz64(r, kk * 2 + bu));
                mma16816(c[0][nb], af0, b0, b1);
                mma16816(c[1][nb], af1, b0, b1);
            }
        }
        __syncthreads();
    }

    if (ROPE) {
#pragma unroll
        for (int mi = 0; mi < 2; mi++) {
#pragma unroll
            for (int rr = 0; rr < 2; rr++) {
                int t = m0 + wm * 32 + mi * 16 + (l >> 2) + rr * 8;
                const float4* tb = g_rope + (size_t)t * 64;
#pragma unroll
                for (int nb = 0; nb < 4; nb++) {
                    int dbase = wn * 32 + nb * 8 + 2 * (l & 3);
                    float4 t0 = tb[dbase];
                    float4 t1 = tb[dbase + 1];
                    float x10 = c[mi][nb][rr * 2],     x11 = c[mi][nb][rr * 2 + 1];
                    float x20 = c[mi][nb + 4][rr * 2], x21 = c[mi][nb + 4][rr * 2 + 1];
                    float y10 = (x10 * t0.x - x20 * t0.y) * mult;
                    float y11 = (x11 * t1.x - x21 * t1.y) * mult;
                    float y20 = (x20 * t0.z + x10 * t0.w) * mult;
                    float y21 = (x21 * t1.z + x11 * t1.w) * mult;
                    __half* yb = Y + (size_t)t * N + n0 + dbase;
                    *(uint32_t*)yb        = packh2(y10, y11);
                    *(uint32_t*)(yb + 64) = packh2(y20, y21);
                }
            }
        }
    } else {
#pragma unroll
        for (int mi = 0; mi < 2; mi++) {
            int gr = m0 + wm * 32 + mi * 16 + (l >> 2);
#pragma unroll
            for (int nb = 0; nb < 8; nb++) {
                int gc = n0 + wn * 32 + (nb & 3) * 8 + (nb >> 2) * 64 + 2 * (l & 3);
                *(float2*)(C + (size_t)gr * N + gc)       = make_float2(c[mi][nb][0], c[mi][nb][1]);
                *(float2*)(C + (size_t)(gr + 8) * N + gc) = make_float2(c[mi][nb][2], c[mi][nb][3]);
            }
        }
    }
}

// Q+K+V projections with fused rope, one launch. 768 blocks range-decoded.
__global__ __launch_bounds__(256, 2)
void proj_qkv() {
    int b = blockIdx.x;
    if (b < 512) {
        hgemm_body<1>(g_xq, g_Wqt, nullptr, g_Qh, T_LEN, QDIM, DIMM, DIMM, 0,
                      b >> 5, b & 31, (float)Q_PREMUL);
    } else if (b < 640) {
        int bb = b - 512;
        hgemm_body<1>(g_xk, g_Wkt, nullptr, g_Kh, T_LEN, KDIM, DIMM, DIMM, 0,
                      bb >> 3, bb & 7, 1.0f);
    } else {
        int bb = b - 640;
        hgemm_body<1>(g_xv, g_Wvt, nullptr, g_Vh, T_LEN, KDIM, DIMM, DIMM, 0,
                      bb >> 3, bb & 7, 1.0f);
    }
}

// O projection split-K=8: grid (2,16,8)
__global__ __launch_bounds__(256, 2)
void hgemm_o(float* __restrict__ Part) {
    hgemm_body<0>(g_Oh, g_Wot, Part + (size_t)blockIdx.z * T_LEN * DIMM, nullptr,
                  T_LEN, DIMM, QDIM, QDIM / 8, blockIdx.z * (QDIM / 8),
                  blockIdx.y, blockIdx.x, 1.0f);
}

__global__ void reduce8_kernel(const float* __restrict__ P, float* __restrict__ out, int n) {
    int i = blockIdx.x * blockDim.x + threadIdx.x;
    if (i * 4 >= n) return;
    float4 r = *(const float4*)(P + i * 4);
#pragma unroll
    for (int s = 1; s < 8; s++) {
        float4 a = *(const float4*)(P + (size_t)s * n + i * 4);
        r.x += a.x; r.y += a.y; r.z += a.z; r.w += a.w;
    }
    *(float4*)(out + i * 4) = r;
}

// ---------------------------------------------------------------------------
// FA-2 attention, Br=128, Bc=64, 8 warps, cp.async double buffer (unchanged).
// ---------------------------------------------------------------------------
#define ATTN_SMEM (32768 + 4 * 16384)   // 98304

__global__ __launch_bounds__(256, 1)
void attn_mma(const __half* __restrict__ Qh, const __half* __restrict__ Kh,
              const __half* __restrict__ Vh, __half* __restrict__ O) {
    extern __shared__ char smem[];
    const uint32_t sm_u = smem_u32(smem);
    const uint32_t sQ_u = sm_u;

    const int tid = threadIdx.x;
    const int w = tid >> 5, l = tid & 31;
    const int qt = gridDim.x - 1 - blockIdx.x;   // longest blocks first
    const int hq = blockIdx.y;
    const int g  = hq >> 2;
    const int nkb = 2 * qt + 2;

    const __half* kg = Kh + (size_t)g * DH_N;
    const __half* vg = Vh + (size_t)g * DH_N;

    {
        const __half* qgp = Qh + (size_t)(qt * 128) * QDIM + hq * DH_N;
#pragma unroll
        for (int i = 0; i < 8; i++) {
            int idx = i * 256 + tid;
            int r = idx >> 4, u = idx & 15;
            cp16(sQ_u + swz(r, u), qgp + (size_t)r * QDIM + u * 8);
        }
#pragma unroll
        for (int i = 0; i < 4; i++) {
            int idx = i * 256 + tid;
            int r = idx >> 4, u = idx & 15;
            cp16(sm_u + 32768 + swz(r, u), kg + (size_t)r * KDIM + u * 8);
            cp16(sm_u + 49152 + swz(r, u), vg + (size_t)r * KDIM + u * 8);
        }
        CP_COMMIT();
    }

    uint32_t qf[8][4];
    float o[16][4];
#pragma unroll
    for (int i = 0; i < 16; i++)
#pragma unroll
        for (int j = 0; j < 4; j++) o[i][j] = 0.f;
    float m0 = -FLT_MAX, m1 = -FLT_MAX, l0 = 0.f, l1 = 0.f;

    const int qrow = w * 16 + (l & 7) + ((l >> 3) & 1) * 8;
    const int qu   = (l >> 4);
    const int krow = ((l >> 4) & 1) * 8 + (l & 7);
    const int ku   = (l >> 3) & 1;
    const int vrow = (l & 7) + ((l >> 3) & 1) * 8;
    const int vu   = (l >> 4) & 1;

    for (int kb = 0; kb < nkb; kb++) {
        const int has_next = (kb + 1 < nkb);
        if (has_next) {
            int tk = kb + 1;
            uint32_t kb_s = sm_u + 32768 + (tk & 1) * 32768;
#pragma unroll
            for (int i = 0; i < 4; i++) {
                int idx = i * 256 + tid;
                int r = idx >> 4, u = idx & 15;
                cp16(kb_s + swz(r, u),         kg + (size_t)(tk * 64 + r) * KDIM + u * 8);
                cp16(kb_s + 16384 + swz(r, u), vg + (size_t)(tk * 64 + r) * KDIM + u * 8);
            }
            CP_COMMIT();
            CP_WAIT(1);
        } else {
            CP_WAIT(0);
        }
        __syncthreads();

        const uint32_t sK_u = sm_u + 32768 + (kb & 1) * 32768;
        const uint32_t sV_u = sK_u + 16384;

        if (kb == 0) {
#pragma unroll
            for (int kk = 0; kk < 8; kk++)
                ldm_x4(qf[kk], sQ_u + swz(qrow, kk * 2 + qu));
        }

        float c[8][4];
#pragma unroll
        for (int nb = 0; nb < 8; nb++)
#pragma unroll
            for (int j = 0; j < 4; j++) c[nb][j] = 0.f;

#pragma unroll
        for (int kk = 0; kk < 8; kk++) {
#pragma unroll
            for (int np = 0; np < 4; np++) {
                uint32_t bf[4];
                ldm_x4(bf, sK_u + swz(np * 16 + krow, kk * 2 + ku));
                mma16816(c[2 * np],     qf[kk], bf[0], bf[1]);
                mma16816(c[2 * np + 1], qf[kk], bf[2], bf[3]);
            }
        }

        if (kb >= 2 * qt) {
            int r0 = qt * 128 + w * 16 + (l >> 2), r1 = r0 + 8;
            int cbase = kb * 64 + 2 * (l & 3);
#pragma unroll
            for (int nb = 0; nb < 8; nb++) {
                int cb = cbase + nb * 8;
                if (cb     > r0) c[nb][0] = -FLT_MAX;
                if (cb + 1 > r0) c[nb][1] = -FLT_MAX;
                if (cb     > r1) c[nb][2] = -FLT_MAX;
                if (cb + 1 > r1) c[nb][3] = -FLT_MAX;
            }
        }

        float mx0 = -FLT_MAX, mx1 = -FLT_MAX;
#pragma unroll
        for (int nb = 0; nb < 8; nb++) {
            mx0 = fmaxf(mx0, fmaxf(c[nb][0], c[nb][1]));
            mx1 = fmaxf(mx1, fmaxf(c[nb][2], c[nb][3]));
        }
        mx0 = fmaxf(mx0, __shfl_xor_sync(0xffffffffu, mx0, 1));
        mx0 = fmaxf(mx0, __shfl_xor_sync(0xffffffffu, mx0, 2));
        mx1 = fmaxf(mx1, __shfl_xor_sync(0xffffffffu, mx1, 1));
        mx1 = fmaxf(mx1, __shfl_xor_sync(0xffffffffu, mx1, 2));

        float mn0 = fmaxf(m0, mx0), mn1 = fmaxf(m1, mx1);
        float a0 = fast_ex2(m0 - mn0);
        float a1 = fast_ex2(m1 - mn1);
        m0 = mn0; m1 = mn1;
        l0 *= a0; l1 *= a1;

        float s0 = 0.f, s1 = 0.f;
#pragma unroll
        for (int nb = 0; nb < 8; nb++) {
            float p;
            p = fast_ex2(c[nb][0] - m0); c[nb][0] = p; s0 += p;
            p = fast_ex2(c[nb][1] - m0); c[nb][1] = p; s0 += p;
            p = fast_ex2(c[nb][2] - m1); c[nb][2] = p; s1 += p;
            p = fast_ex2(c[nb][3] - m1); c[nb][3] = p; s1 += p;
        }
        s0 += __shfl_xor_sync(0xffffffffu, s0, 1);
        s0 += __shfl_xor_sync(0xffffffffu, s0, 2);
        s1 += __shfl_xor_sync(0xffffffffu, s1, 1);
        s1 += __shfl_xor_sync(0xffffffffu, s1, 2);
        l0 += s0; l1 += s1;

#pragma unroll
        for (int i = 0; i < 16; i++) {
            o[i][0] *= a0; o[i][1] *= a0;
            o[i][2] *= a1; o[i][3] *= a1;
        }

        uint32_t pf[4][4];
#pragma unroll
        for (int k2 = 0; k2 < 4; k2++) {
            pf[k2][0] = packh2(c[2 * k2][0],     c[2 * k2][1]);
            pf[k2][1] = packh2(c[2 * k2][2],     c[2 * k2][3]);
            pf[k2][2] = packh2(c[2 * k2 + 1][0], c[2 * k2 + 1][1]);
            pf[k2][3] = packh2(c[2 * k2 + 1][2], c[2 * k2 + 1][3]);
        }

#pragma unroll
        for (int k2 = 0; k2 < 4; k2++) {
            int row = k2 * 16 + vrow;
#pragma unroll
            for (int np = 0; np < 8; np++) {
                uint32_t bf[4];
                ldm_x4t(bf, sV_u + swz(row, np * 2 + vu));
                mma16816(o[2 * np],     pf[k2], bf[0], bf[1]);
                mma16816(o[2 * np + 1], pf[k2], bf[2], bf[3]);
            }
        }
        __syncthreads();
    }

    {
        float inv0 = 1.f / l0, inv1 = 1.f / l1;
        int gr0 = qt * 128 + w * 16 + (l >> 2), gr1 = gr0 + 8;
        __half* ob0 = O + (size_t)gr0 * QDIM + hq * DH_N + 2 * (l & 3);
        __half* ob1 = O + (size_t)gr1 * QDIM + hq * DH_N + 2 * (l & 3);
#pragma unroll
        for (int nb2 = 0; nb2 < 16; nb2++) {
            *(uint32_t*)(ob0 + nb2 * 8) = packh2(o[nb2][0] * inv0, o[nb2][1] * inv0);
            *(uint32_t*)(ob1 + nb2 * 8) = packh2(o[nb2][2] * inv1, o[nb2][3] * inv1);
        }
    }
}

// ---------------------------------------------------------------------------
// Launch
// ---------------------------------------------------------------------------
extern "C" void kernel_launch(void* const* d_in, const int* in_sizes, int n_in,
                              void* d_out, int out_size) {
    const float* q  = (const float*)d_in[0];
    const float* k  = (const float*)d_in[1];
    const float* v  = (const float*)d_in[2];
    // d_in[3] = mask (causal, reconstructed analytically)
    const float* Wq = (const float*)d_in[4];
    const float* Wk = (const float*)d_in[5];
    const float* Wv = (const float*)d_in[6];
    const float* Wo = (const float*)d_in[7];
    float* out = (float*)d_out;

    float* Part;
    __half *Qh, *Kh, *Vh, *Oh;
    cudaGetSymbolAddress((void**)&Qh, g_Qh);
    cudaGetSymbolAddress((void**)&Kh, g_Kh);
    cudaGetSymbolAddress((void**)&Vh, g_Vh);
    cudaGetSymbolAddress((void**)&Oh, g_Oh);
    cudaGetSymbolAddress((void**)&Part, g_part);

    cudaFuncSetAttribute(attn_mma, cudaFuncAttributeMaxDynamicSharedMemorySize, ATTN_SMEM);
    cudaFuncSetAttribute(proj_qkv, cudaFuncAttributeMaxDynamicSharedMemorySize, GEMM_SMEM);
    cudaFuncSetAttribute(hgemm_o,  cudaFuncAttributeMaxDynamicSharedMemorySize, GEMM_SMEM);

    // prep
    castall_kernel<<<dim3(512, 1, 3), 256>>>(q, k, v);
    tcastall_kernel<<<2560, 256>>>(Wq, Wk, Wv, Wo);

    // Q/K/V projections with fused rope (one launch)
    proj_qkv<<<768, 256, GEMM_SMEM>>>();

    // attention
    attn_mma<<<dim3(T_LEN / 128, HQ_N), 256, ATTN_SMEM>>>(Qh, Kh, Vh, Oh);

    // output projection split-K=8 + reduce
    hgemm_o<<<dim3(2, 16, 8), 256, GEMM_SMEM>>>(Part);
    reduce8_kernel<<<(T_LEN * DIMM / 4 + 255) / 256, 256>>>(Part, out, T_LEN * DIMM);
}

// round 8
// speedup vs baseline: 8.3877x; 1.0359x over previous
#include <cuda_runtime.h>
#include <cuda_fp16.h>
#include <math.h>
#include <float.h>
#include <stdint.h>

// ---------------------------------------------------------------------------
// Problem constants
// ---------------------------------------------------------------------------
#define T_LEN 2048
#define DIMM  256
#define HQ_N  32
#define HK_N  8
#define DH_N  128
#define QDIM  (HQ_N * DH_N)   // 4096
#define KDIM  (HK_N * DH_N)   // 1024

#define Q_PREMUL (0.08838834764831845 * 1.4426950408889634)

// Scratch (no cudaMalloc allowed)
__device__ __align__(16) __half g_Qh[T_LEN * QDIM];
__device__ __align__(16) __half g_Kh[T_LEN * KDIM];
__device__ __align__(16) __half g_Vh[T_LEN * KDIM];
__device__ __align__(16) __half g_Oh[T_LEN * QDIM];
__device__ __align__(16) __half g_xq[T_LEN * DIMM];
__device__ __align__(16) __half g_xk[T_LEN * DIMM];
__device__ __align__(16) __half g_xv[T_LEN * DIMM];
__device__ __align__(16) __half g_Wqt[QDIM * DIMM];
__device__ __align__(16) __half g_Wkt[KDIM * DIMM];
__device__ __align__(16) __half g_Wvt[KDIM * DIMM];
__device__ __align__(16) __half g_Wot[DIMM * QDIM];
__device__ __align__(16) float  g_part[8 * T_LEN * DIMM];
__device__ __align__(16) float4 g_rope[T_LEN * 64];   // (cos1,sin1,cos2,sin2)

// ---------------------------------------------------------------------------
// PTX helpers
// ---------------------------------------------------------------------------
__device__ __forceinline__ uint32_t smem_u32(const void* p) {
    uint32_t a;
    asm("{ .reg .u64 t; cvta.to.shared.u64 t, %1; cvt.u32.u64 %0, t; }" : "=r"(a) : "l"(p));
    return a;
}
__device__ __forceinline__ void ldm_x4(uint32_t* r, uint32_t addr) {
    asm volatile("ldmatrix.sync.aligned.m8n8.x4.shared.b16 {%0,%1,%2,%3}, [%4];"
                 : "=r"(r[0]), "=r"(r[1]), "=r"(r[2]), "=r"(r[3]) : "r"(addr));
}
__device__ __forceinline__ void ldm_x2(uint32_t& r0, uint32_t& r1, uint32_t addr) {
    asm volatile("ldmatrix.sync.aligned.m8n8.x2.shared.b16 {%0,%1}, [%2];"
                 : "=r"(r0), "=r"(r1) : "r"(addr));
}
__device__ __forceinline__ void ldm_x4t(uint32_t* r, uint32_t addr) {
    asm volatile("ldmatrix.sync.aligned.m8n8.x4.trans.shared.b16 {%0,%1,%2,%3}, [%4];"
                 : "=r"(r[0]), "=r"(r[1]), "=r"(r[2]), "=r"(r[3]) : "r"(addr));
}
__device__ __forceinline__ void mma16816(float* c, const uint32_t* a, uint32_t b0, uint32_t b1) {
    asm volatile(
        "mma.sync.aligned.m16n8k16.row.col.f32.f16.f16.f32 "
        "{%0,%1,%2,%3}, {%4,%5,%6,%7}, {%8,%9}, {%0,%1,%2,%3};"
        : "+f"(c[0]), "+f"(c[1]), "+f"(c[2]), "+f"(c[3])
        : "r"(a[0]), "r"(a[1]), "r"(a[2]), "r"(a[3]), "r"(b0), "r"(b1));
}
__device__ __forceinline__ uint32_t packh2(float lo, float hi) {
    __half2 h = __float22half2_rn(make_float2(lo, hi));
    return *(uint32_t*)&h;
}
__device__ __forceinline__ float fast_ex2(float x) {
    float y;
    asm("ex2.approx.ftz.f32 %0, %1;" : "=f"(y) : "f"(x));
    return y;
}
__device__ __forceinline__ void cp16(uint32_t saddr, const void* g) {
    asm volatile("cp.async.cg.shared.global [%0], [%1], 16;" :: "r"(saddr), "l"(g));
}
#define CP_COMMIT() asm volatile("cp.async.commit_group;" ::: "memory")
#define CP_WAIT(n)  asm volatile("cp.async.wait_group %0;" :: "n"(n) : "memory")

__device__ __forceinline__ uint32_t swz(int r, int u) {
    return (uint32_t)(r * 256 + (((u & 8) | ((u ^ r) & 7)) << 4));
}
__device__ __forceinline__ uint32_t swz64(int r, int u) {
    return (uint32_t)(r * 128 + (((u ^ r) & 7) << 4));
}

// ---------------------------------------------------------------------------
// Fused prep: input casts + rope table (blocks 0..1535) and all 4 weight
// transposes+casts (blocks 1536..4095). 256 threads everywhere.
// ---------------------------------------------------------------------------
__global__ void prep_kernel(const float* __restrict__ q, const float* __restrict__ k,
                            const float* __restrict__ v,
                            const float* __restrict__ Wq, const float* __restrict__ Wk,
                            const float* __restrict__ Wv, const float* __restrict__ Wo) {
    __shared__ float t[32][33];
    int b = blockIdx.x;
    if (b < 1536) {
        int z = b >> 9;                       // 0,1,2 -> q,k,v
        int i = (b & 511) * 256 + threadIdx.x;
        if (z == 0) {
            // rope table: exactly 512*256 = 131072 = T_LEN*64 entries
            int tt = i >> 6, d = i & 63;
            double pos = 6144.0 + (double)tt;
            double if1 = pow(10000.0, -(double)d / 128.0);
            double if2 = pow(10000.0, -(double)(d + 64) / 128.0);
            double f1 = pos * if1, f2 = pos * if2;
            const double inv2pi = 0.15915494309189535;
            const double twopi  = 6.283185307179586;
            f1 -= floor(f1 * inv2pi) * twopi;
            f2 -= floor(f2 * inv2pi) * twopi;
            float s1, c1, s2, c2;
            sincosf((float)f1, &s1, &c1);
            sincosf((float)f2, &s2, &c2);
            g_rope[i] = make_float4(c1, s1, c2, s2);
        }
        const float* X = (z == 0) ? q : (z == 1) ? k : v;
        __half* Y = (z == 0) ? g_xq : (z == 1) ? g_xk : g_xv;
        float4 val = *(const float4*)(X + i * 4);
        __half2 a = __float22half2_rn(make_float2(val.x, val.y));
        __half2 bb = __float22half2_rn(make_float2(val.z, val.w));
        *(uint32_t*)(Y + i * 4)     = *(uint32_t*)&a;
        *(uint32_t*)(Y + i * 4 + 2) = *(uint32_t*)&bb;
    } else {
        b -= 1536;
        const float* W; __half* Wt; int K, N, ntile_n, tt;
        if (b < 1024)      { W = Wq; Wt = g_Wqt; K = DIMM; N = QDIM; ntile_n = 128; tt = b; }
        else if (b < 1280) { W = Wk; Wt = g_Wkt; K = DIMM; N = KDIM; ntile_n = 32;  tt = b - 1024; }
        else if (b < 1536) { W = Wv; Wt = g_Wvt; K = DIMM; N = KDIM; ntile_n = 32;  tt = b - 1280; }
        else               { W = Wo; Wt = g_Wot; K = QDIM; N = DIMM; ntile_n = 8;   tt = b - 1536; }
        int n0 = (tt % ntile_n) * 32, k0 = (tt / ntile_n) * 32;
        int tx = threadIdx.x & 31, ty = threadIdx.x >> 5;
#pragma unroll
        for (int i = 0; i < 4; i++)
            t[ty + i * 8][tx] = W[(size_t)(k0 + ty + i * 8) * N + n0 + tx];
        __syncthreads();
#pragma unroll
        for (int i = 0; i < 4; i++)
            Wt[(size_t)(n0 + ty + i * 8) * K + k0 + tx] = __float2half_rn(t[tx][ty + i * 8]);
    }
}

// ---------------------------------------------------------------------------
// Pipelined fp16 GEMM body (unchanged from round 7).
// ---------------------------------------------------------------------------
#define GEMM_SMEM 65536

__device__ __forceinline__
void gemm_load(uint32_t sbuf, const __half* Ab, const __half* Bb, int K, int tid) {
    int lr = tid >> 3, lu = tid & 7;
#pragma unroll
    for (int i = 0; i < 4; i++) {
        int r = i * 32 + lr;
        cp16(sbuf + swz64(r, lu),         Ab + (size_t)r * K + lu * 8);
        cp16(sbuf + 16384 + swz64(r, lu), Bb + (size_t)r * K + lu * 8);
    }
}

template <int ROPE>
__device__ __forceinline__
void hgemm_body(const __half* __restrict__ A, const __half* __restrict__ Bt,
                float* __restrict__ C, __half* __restrict__ Y,
                int M, int N, int K, int klen, int kstart,
                int m_t, int n_t, float mult) {
    extern __shared__ char ds[];
    const uint32_t s_u = smem_u32(ds);

    const int tid = threadIdx.x;
    const int w = tid >> 5, l = tid & 31;
    const int wm = w >> 1, wn = w & 1;
    const int m0 = m_t * 128, n0 = n_t * 128;
    const int nk = klen >> 6;

    const __half* Ab = A + (size_t)m0 * K + kstart;
    const __half* Bb = Bt + (size_t)n0 * K + kstart;

    gemm_load(s_u, Ab, Bb, K, tid);
    CP_COMMIT();

    float c[2][8][4];
#pragma unroll
    for (int mi = 0; mi < 2; mi++)
#pragma unroll
        for (int nb = 0; nb < 8; nb++)
#pragma unroll
            for (int j = 0; j < 4; j++) c[mi][nb][j] = 0.f;

    const int arow = wm * 32 + (l & 7) + ((l >> 3) & 1) * 8;
    const int au = l >> 4;
    const int brow = wn * 32 + (l & 7);
    const int bu = (l >> 3) & 1;

    for (int i = 0; i < nk; i++) {
        if (i + 1 < nk) {
            gemm_load(s_u + ((i + 1) & 1) * 32768, Ab + (i + 1) * 64, Bb + (i + 1) * 64, K, tid);
            CP_COMMIT();
            CP_WAIT(1);
        } else {
            CP_WAIT(0);
        }
        __syncthreads();

        uint32_t sA_u = s_u + (i & 1) * 32768;
        uint32_t sB_u = sA_u + 16384;
#pragma unroll
        for (int kk = 0; kk < 4; kk++) {
            uint32_t af0[4], af1[4];
            ldm_x4(af0, sA_u + swz64(arow,      kk * 2 + au));
            ldm_x4(af1, sA_u + swz64(arow + 16, kk * 2 + au));
#pragma unroll
            for (int nb = 0; nb < 8; nb++) {
                int r = brow + (nb & 3) * 8 + (nb >> 2) * 64;
                uint32_t b0, b1;
                ldm_x2(b0, b1, sB_u + swz64(r, kk * 2 + bu));
                mma16816(c[0][nb], af0, b0, b1);
                mma16816(c[1][nb], af1, b0, b1);
            }
        }
        __syncthreads();
    }

    if (ROPE) {
#pragma unroll
        for (int mi = 0; mi < 2; mi++) {
#pragma unroll
            for (int rr = 0; rr < 2; rr++) {
                int t = m0 + wm * 32 + mi * 16 + (l >> 2) + rr * 8;
                const float4* tb = g_rope + (size_t)t * 64;
#pragma unroll
                for (int nb = 0; nb < 4; nb++) {
                    int dbase = wn * 32 + nb * 8 + 2 * (l & 3);
                    float4 t0 = tb[dbase];
                    float4 t1 = tb[dbase + 1];
                    float x10 = c[mi][nb][rr * 2],     x11 = c[mi][nb][rr * 2 + 1];
                    float x20 = c[mi][nb + 4][rr * 2], x21 = c[mi][nb + 4][rr * 2 + 1];
                    float y10 = (x10 * t0.x - x20 * t0.y) * mult;
                    float y11 = (x11 * t1.x - x21 * t1.y) * mult;
                    float y20 = (x20 * t0.z + x10 * t0.w) * mult;
                    float y21 = (x21 * t1.z + x11 * t1.w) * mult;
                    __half* yb = Y + (size_t)t * N + n0 + dbase;
                    *(uint32_t*)yb        = packh2(y10, y11);
                    *(uint32_t*)(yb + 64) = packh2(y20, y21);
                }
            }
        }
    } else {
#pragma unroll
        for (int mi = 0; mi < 2; mi++) {
            int gr = m0 + wm * 32 + mi * 16 + (l >> 2);
#pragma unroll
            for (int nb = 0; nb < 8; nb++) {
                int gc = n0 + wn * 32 + (nb & 3) * 8 + (nb >> 2) * 64 + 2 * (l & 3);
                *(float2*)(C + (size_t)gr * N + gc)       = make_float2(c[mi][nb][0], c[mi][nb][1]);
                *(float2*)(C + (size_t)(gr + 8) * N + gc) = make_float2(c[mi][nb][2], c[mi][nb][3]);
            }
        }
    }
}

__global__ __launch_bounds__(256, 2)
void proj_qkv() {
    int b = blockIdx.x;
    if (b < 512) {
        hgemm_body<1>(g_xq, g_Wqt, nullptr, g_Qh, T_LEN, QDIM, DIMM, DIMM, 0,
                      b >> 5, b & 31, (float)Q_PREMUL);
    } else if (b < 640) {
        int bb = b - 512;
        hgemm_body<1>(g_xk, g_Wkt, nullptr, g_Kh, T_LEN, KDIM, DIMM, DIMM, 0,
                      bb >> 3, bb & 7, 1.0f);
    } else {
        int bb = b - 640;
        hgemm_body<1>(g_xv, g_Wvt, nullptr, g_Vh, T_LEN, KDIM, DIMM, DIMM, 0,
                      bb >> 3, bb & 7, 1.0f);
    }
}

__global__ __launch_bounds__(256, 2)
void hgemm_o(float* __restrict__ Part) {
    hgemm_body<0>(g_Oh, g_Wot, Part + (size_t)blockIdx.z * T_LEN * DIMM, nullptr,
                  T_LEN, DIMM, QDIM, QDIM / 8, blockIdx.z * (QDIM / 8),
                  blockIdx.y, blockIdx.x, 1.0f);
}

__global__ void reduce8_kernel(const float* __restrict__ P, float* __restrict__ out, int n) {
    int i = blockIdx.x * blockDim.x + threadIdx.x;
    if (i * 4 >= n) return;
    float4 r = *(const float4*)(P + i * 4);
#pragma unroll
    for (int s = 1; s < 8; s++) {
        float4 a = *(const float4*)(P + (size_t)s * n + i * 4);
        r.x += a.x; r.y += a.y; r.z += a.z; r.w += a.w;
    }
    *(float4*)(out + i * 4) = r;
}

// ---------------------------------------------------------------------------
// FA-2 attention, Br=128, Bc=64, 8 warps, 3-stage cp.async circular buffer,
// ONE __syncthreads per tile (3 stages make ≤1-tile warp skew safe, letting
// softmax of lagging warps overlap MMA of leading warps).
// SMEM: Q 32KB @0; K/V stage s in {0,1,2}: K @32768+s*32768, V @+16384.
// ---------------------------------------------------------------------------
#define ATTN_SMEM (32768 + 6 * 16384)   // 131072

__global__ __launch_bounds__(256, 1)
void attn_mma(const __half* __restrict__ Qh, const __half* __restrict__ Kh,
              const __half* __restrict__ Vh, __half* __restrict__ O) {
    extern __shared__ char smem[];
    const uint32_t sm_u = smem_u32(smem);
    const uint32_t sQ_u = sm_u;

    const int tid = threadIdx.x;
    const int w = tid >> 5, l = tid & 31;
    const int qt = gridDim.x - 1 - blockIdx.x;   // longest blocks first
    const int hq = blockIdx.y;
    const int g  = hq >> 2;
    const int nkb = 2 * qt + 2;

    const __half* kg = Kh + (size_t)g * DH_N;
    const __half* vg = Vh + (size_t)g * DH_N;

    // prefetch Q + tile 0 (into stage 0) as group 0
    {
        const __half* qgp = Qh + (size_t)(qt * 128) * QDIM + hq * DH_N;
#pragma unroll
        for (int i = 0; i < 8; i++) {
            int idx = i * 256 + tid;
            int r = idx >> 4, u = idx & 15;
            cp16(sQ_u + swz(r, u), qgp + (size_t)r * QDIM + u * 8);
        }
#pragma unroll
        for (int i = 0; i < 4; i++) {
            int idx = i * 256 + tid;
            int r = idx >> 4, u = idx & 15;
            cp16(sm_u + 32768 + swz(r, u), kg + (size_t)r * KDIM + u * 8);
            cp16(sm_u + 49152 + swz(r, u), vg + (size_t)r * KDIM + u * 8);
        }
        CP_COMMIT();
    }

    uint32_t qf[8][4];
    float o[16][4];
#pragma unroll
    for (int i = 0; i < 16; i++)
#pragma unroll
        for (int j = 0; j < 4; j++) o[i][j] = 0.f;
    float m0 = -FLT_MAX, m1 = -FLT_MAX, l0 = 0.f, l1 = 0.f;

    const int qrow = w * 16 + (l & 7) + ((l >> 3) & 1) * 8;
    const int qu   = (l >> 4);
    const int krow = ((l >> 4) & 1) * 8 + (l & 7);
    const int ku   = (l >> 3) & 1;
    const int vrow = (l & 7) + ((l >> 3) & 1) * 8;
    const int vu   = (l >> 4) & 1;

    int buf = 0;   // stage holding tile kb
    for (int kb = 0; kb < nkb; kb++) {
        if (kb + 1 < nkb) {
            int pbuf = (buf == 2) ? 0 : buf + 1;
            int tk = kb + 1;
            uint32_t kb_s = sm_u + 32768 + pbuf * 32768;
#pragma unroll
            for (int i = 0; i < 4; i++) {
                int idx = i * 256 + tid;
                int r = idx >> 4, u = idx & 15;
                cp16(kb_s + swz(r, u),         kg + (size_t)(tk * 64 + r) * KDIM + u * 8);
                cp16(kb_s + 16384 + swz(r, u), vg + (size_t)(tk * 64 + r) * KDIM + u * 8);
            }
            CP_COMMIT();
            CP_WAIT(1);
        } else {
            CP_WAIT(0);
        }
        __syncthreads();   // the only barrier per tile

        const uint32_t sK_u = sm_u + 32768 + buf * 32768;
        const uint32_t sV_u = sK_u + 16384;
        buf = (buf == 2) ? 0 : buf + 1;

        if (kb == 0) {
#pragma unroll
            for (int kk = 0; kk < 8; kk++)
                ldm_x4(qf[kk], sQ_u + swz(qrow, kk * 2 + qu));
        }

        float c[8][4];
#pragma unroll
        for (int nb = 0; nb < 8; nb++)
#pragma unroll
            for (int j = 0; j < 4; j++) c[nb][j] = 0.f;

#pragma unroll
        for (int kk = 0; kk < 8; kk++) {
#pragma unroll
            for (int np = 0; np < 4; np++) {
                uint32_t bf[4];
                ldm_x4(bf, sK_u + swz(np * 16 + krow, kk * 2 + ku));
                mma16816(c[2 * np],     qf[kk], bf[0], bf[1]);
                mma16816(c[2 * np + 1], qf[kk], bf[2], bf[3]);
            }
        }

        if (kb >= 2 * qt) {
            int r0 = qt * 128 + w * 16 + (l >> 2), r1 = r0 + 8;
            int cbase = kb * 64 + 2 * (l & 3);
#pragma unroll
            for (int nb = 0; nb < 8; nb++) {
                int cb = cbase + nb * 8;
                if (cb     > r0) c[nb][0] = -FLT_MAX;
                if (cb + 1 > r0) c[nb][1] = -FLT_MAX;
                if (cb     > r1) c[nb][2] = -FLT_MAX;
                if (cb + 1 > r1) c[nb][3] = -FLT_MAX;
            }
        }

        float mx0 = -FLT_MAX, mx1 = -FLT_MAX;
#pragma unroll
        for (int nb = 0; nb < 8; nb++) {
            mx0 = fmaxf(mx0, fmaxf(c[nb][0], c[nb][1]));
            mx1 = fmaxf(mx1, fmaxf(c[nb][2], c[nb][3]));
        }
        mx0 = fmaxf(mx0, __shfl_xor_sync(0xffffffffu, mx0, 1));
        mx0 = fmaxf(mx0, __shfl_xor_sync(0xffffffffu, mx0, 2));
        mx1 = fmaxf(mx1, __shfl_xor_sync(0xffffffffu, mx1, 1));
        mx1 = fmaxf(mx1, __shfl_xor_sync(0xffffffffu, mx1, 2));

        float mn0 = fmaxf(m0, mx0), mn1 = fmaxf(m1, mx1);
        float a0 = fast_ex2(m0 - mn0);
        float a1 = fast_ex2(m1 - mn1);
        m0 = mn0; m1 = mn1;
        l0 *= a0; l1 *= a1;

        float s0 = 0.f, s1 = 0.f;
#pragma unroll
        for (int nb = 0; nb < 8; nb++) {
            float p;
            p = fast_ex2(c[nb][0] - m0); c[nb][0] = p; s0 += p;
            p = fast_ex2(c[nb][1] - m0); c[nb][1] = p; s0 += p;
            p = fast_ex2(c[nb][2] - m1); c[nb][2] = p; s1 += p;
            p = fast_ex2(c[nb][3] - m1); c[nb][3] = p; s1 += p;
        }
        s0 += __shfl_xor_sync(0xffffffffu, s0, 1);
        s0 += __shfl_xor_sync(0xffffffffu, s0, 2);
        s1 += __shfl_xor_sync(0xffffffffu, s1, 1);
        s1 += __shfl_xor_sync(0xffffffffu, s1, 2);
        l0 += s0; l1 += s1;

#pragma unroll
        for (int i = 0; i < 16; i++) {
            o[i][0] *= a0; o[i][1] *= a0;
            o[i][2] *= a1; o[i][3] *= a1;
        }

        uint32_t pf[4][4];
#pragma unroll
        for (int k2 = 0; k2 < 4; k2++) {
            pf[k2][0] = packh2(c[2 * k2][0],     c[2 * k2][1]);
            pf[k2][1] = packh2(c[2 * k2][2],     c[2 * k2][3]);
            pf[k2][2] = packh2(c[2 * k2 + 1][0], c[2 * k2 + 1][1]);
            pf[k2][3] = packh2(c[2 * k2 + 1][2], c[2 * k2 + 1][3]);
        }

#pragma unroll
        for (int k2 = 0; k2 < 4; k2++) {
            int row = k2 * 16 + vrow;
#pragma unroll
            for (int np = 0; np < 8; np++) {
                uint32_t bf[4];
                ldm_x4t(bf, sV_u + swz(row, np * 2 + vu));
                mma16816(o[2 * np],     pf[k2], bf[0], bf[1]);
                mma16816(o[2 * np + 1], pf[k2], bf[2], bf[3]);
            }
        }
        // NO trailing __syncthreads: 3-stage buffer tolerates ≤1-tile skew.
    }

    {
        float inv0 = 1.f / l0, inv1 = 1.f / l1;
        int gr0 = qt * 128 + w * 16 + (l >> 2), gr1 = gr0 + 8;
        __half* ob0 = O + (size_t)gr0 * QDIM + hq * DH_N + 2 * (l & 3);
        __half* ob1 = O + (size_t)gr1 * QDIM + hq * DH_N + 2 * (l & 3);
#pragma unroll
        for (int nb2 = 0; nb2 < 16; nb2++) {
            *(uint32_t*)(ob0 + nb2 * 8) = packh2(o[nb2][0] * inv0, o[nb2][1] * inv0);
            *(uint32_t*)(ob1 + nb2 * 8) = packh2(o[nb2][2] * inv1, o[nb2][3] * inv1);
        }
    }
}

// ---------------------------------------------------------------------------
// Launch
// ---------------------------------------------------------------------------
extern "C" void kernel_launch(void* const* d_in, const int* in_sizes, int n_in,
                              void* d_out, int out_size) {
    const float* q  = (const float*)d_in[0];
    const float* k  = (const float*)d_in[1];
    const float* v  = (const float*)d_in[2];
    // d_in[3] = mask (causal, reconstructed analytically)
    const float* Wq = (const float*)d_in[4];
    const float* Wk = (const float*)d_in[5];
    const float* Wv = (const float*)d_in[6];
    const float* Wo = (const float*)d_in[7];
    float* out = (float*)d_out;

    float* Part;
    __half *Qh, *Kh, *Vh, *Oh;
    cudaGetSymbolAddress((void**)&Qh, g_Qh);
    cudaGetSymbolAddress((void**)&Kh, g_Kh);
    cudaGetSymbolAddress((void**)&Vh, g_Vh);
    cudaGetSymbolAddress((void**)&Oh, g_Oh);
    cudaGetSymbolAddress((void**)&Part, g_part);

    cudaFuncSetAttribute(attn_mma, cudaFuncAttributeMaxDynamicSharedMemorySize, ATTN_SMEM);
    cudaFuncSetAttribute(proj_qkv, cudaFuncAttributeMaxDynamicSharedMemorySize, GEMM_SMEM);
    cudaFuncSetAttribute(hgemm_o,  cudaFuncAttributeMaxDynamicSharedMemorySize, GEMM_SMEM);

    // fused prep (casts + rope table + weight transposes)
    prep_kernel<<<4096, 256>>>(q, k, v, Wq, Wk, Wv, Wo);

    // Q/K/V projections with fused rope
    proj_qkv<<<768, 256, GEMM_SMEM>>>();

    // attention
    attn_mma<<<dim3(T_LEN / 128, HQ_N), 256, ATTN_SMEM>>>(Qh, Kh, Vh, Oh);

    // output projection split-K=8 + reduce
    hgemm_o<<<dim3(2, 16, 8), 256, GEMM_SMEM>>>(Part);
    reduce8_kernel<<<(T_LEN * DIMM / 4 + 255) / 256, 256>>>(Part, out, T_LEN * DIMM);
}